// round 7
// baseline (speedup 1.0000x reference)
#include <cuda_runtime.h>
#include <math.h>
#include <stdint.h>

// ---------------- problem constants ----------------
#define B_TOK 4096
#define DIN   512
#define PP    1024
#define HH    2048
#define EE    8
#define HSH   4096
#define OUTN  29
#define CAP   4096

// ---------------- int8 GEMM tile config ----------------
#define BM 128
#define BN 128
#define KC 64                      // int8 k elems per chunk (64 bytes per row)
#define ROWB 80                    // smem row stride (64B data + 16B pad)
#define OFF_A1 0
#define OFF_A0 (128 * ROWB)
#define OFF_B1 (256 * ROWB)
#define OFF_B0 (384 * ROWB)
#define STAGE_BYTES (512 * ROWB)   // 40960
#define NSTAGE 3
#define SMEM_BYTES (NSTAGE * STAGE_BYTES) // 122880

// quant: q = round(v * 16256 / S); v ~= S*(128*a1 + a0)/16256 ; a1 in +-127, a0 in +-64
#define QSCL 16256.0f
#define C2F  (1.0f / 16129.0f)     // 16384 / 16256^2
#define C1F  (1.0f / 2064512.0f)   // 128   / 16256^2

// ---------------- PTX helpers ----------------
__device__ __forceinline__ uint32_t smem_u32(const void* p) {
    uint32_t a;
    asm("{ .reg .u64 t; cvta.to.shared.u64 t, %1; cvt.u32.u64 %0, t; }" : "=r"(a) : "l"(p));
    return a;
}
#define CP16(dst, src) asm volatile("cp.async.cg.shared.global [%0], [%1], 16;" :: "r"(dst), "l"(src) : "memory")
#define CP_COMMIT()    asm volatile("cp.async.commit_group;" ::: "memory")

#define LDSM4(r, addr) \
    asm volatile("ldmatrix.sync.aligned.m8n8.x4.shared.b16 {%0,%1,%2,%3}, [%4];" \
        : "=r"((r)[0]), "=r"((r)[1]), "=r"((r)[2]), "=r"((r)[3]) : "r"(addr))

#define MMA_S8(c, a, b0, b1) \
    asm volatile("mma.sync.aligned.m16n8k32.row.col.s32.s8.s8.s32 " \
        "{%0,%1,%2,%3}, {%4,%5,%6,%7}, {%8,%9}, {%0,%1,%2,%3};" \
        : "+r"((c)[0]), "+r"((c)[1]), "+r"((c)[2]), "+r"((c)[3]) \
        : "r"((a)[0]), "r"((a)[1]), "r"((a)[2]), "r"((a)[3]), "r"(b0), "r"(b1))

// ---------------- scratch (device globals) ----------------
#define DEV __device__ __align__(128)
// activations: fp32 + int8 digit pairs + per-row scales
DEV int8_t g_x1 [B_TOK * DIN],      g_x0 [B_TOK * DIN];      DEV float g_sx [B_TOK];
DEV float  g_p32[B_TOK * PP];
DEV int8_t g_p1 [B_TOK * PP],       g_p0 [B_TOK * PP];       DEV float g_sp [B_TOK];
DEV int8_t g_ap1[EE * CAP * PP],    g_ap0[EE * CAP * PP];    DEV float g_sap[EE * CAP];
DEV float  g_h32[(size_t)EE * CAP * HH];
DEV int8_t g_hq1[(size_t)EE * CAP * HH], g_hq0[(size_t)EE * CAP * HH]; DEV float g_sh[EE * CAP];
DEV float  g_eo32[(size_t)EE * CAP * PP];
DEV float  g_moe [B_TOK * PP];
DEV float  g_sg32[(size_t)B_TOK * HSH];
DEV float  g_su32[(size_t)B_TOK * HSH];
DEV int8_t g_su1[(size_t)B_TOK * HSH], g_su0[(size_t)B_TOK * HSH]; DEV float g_ssu[B_TOK];
DEV float  g_cb32[B_TOK * PP];
DEV int8_t g_cb1[B_TOK * PP],       g_cb0[B_TOK * PP];       DEV float g_scb[B_TOK];
DEV float  g_h132[B_TOK * HH];
DEV int8_t g_h11[B_TOK * HH],       g_h10[B_TOK * HH];       DEV float g_sh1[B_TOK];
DEV float  g_h232[B_TOK * HH];
// weights: transposed int8 digit pairs + per-out-column scales
DEV int8_t g_wp1 [PP * DIN],        g_wp0 [PP * DIN];        DEV float g_swp [PP];
DEV int8_t g_w11 [EE * HH * PP],    g_w10 [EE * HH * PP];    DEV float g_sw1 [EE * HH];
DEV int8_t g_w21 [EE * PP * HH],    g_w20 [EE * PP * HH];    DEV float g_sw2 [EE * PP];
DEV int8_t g_sgw1[HSH * PP],        g_sgw0[HSH * PP];        DEV float g_ssgw[HSH];
DEV int8_t g_suw1[HSH * PP],        g_suw0[HSH * PP];        DEV float g_ssuw[HSH];
DEV int8_t g_sdw1[PP * HSH],        g_sdw0[PP * HSH];        DEV float g_ssdw[PP];
DEV int8_t g_m11 [HH * PP],         g_m10 [HH * PP];         DEV float g_sm1 [HH];
DEV int8_t g_m21 [HH * HH],         g_m20 [HH * HH];         DEV float g_sm2 [HH];
// router
DEV int   g_counts[EE];
DEV int   g_slot_token[EE * CAP];
DEV int   g_pair_slot[B_TOK * 2];
DEV float g_pair_gate[B_TOK * 2];

__device__ __forceinline__ float silu_f(float x) { return x / (1.0f + expf(-x)); }

// ---------------- stage fill: A 128 rows + B 128 rows, 64B/row, 2 digits ----------------
__device__ __forceinline__ void fill_stage(uint32_t st, int tid,
    const int8_t* A1, const int8_t* A0, const int8_t* B1, const int8_t* B0,
    size_t Kb, long rowA0, long rowB0, size_t kByte)
{
#pragma unroll
    for (int i = 0; i < 2; i++) {                  // A: 128 rows x 4 x 16B
        int p = tid + (i << 8);
        int row = p >> 2, ch = p & 3;
        uint32_t d = st + row * ROWB + ch * 16;
        size_t s = (size_t)(rowA0 + row) * Kb + kByte + ch * 16;
        CP16(d + OFF_A1, A1 + s);
        CP16(d + OFF_A0, A0 + s);
    }
#pragma unroll
    for (int i = 0; i < 2; i++) {                  // B: 128 rows
        int p = tid + (i << 8);
        int row = p >> 2, ch = p & 3;
        uint32_t d = st + row * ROWB + ch * 16;
        size_t s = (size_t)(rowB0 + row) * Kb + kByte + ch * 16;
        CP16(d + OFF_B1, B1 + s);
        CP16(d + OFF_B0, B0 + s);
    }
    CP_COMMIT();
}

// ---------------- int8 two-digit GEMM (IMMA m16n8k32) ----------------
// C = epi(sA_i * sB_j * (C2F*P2 + C1F*P1) + bias)
// P2 = sum a1*b1 ; P1 = sum (a1*b0 + a0*b1) ; a0*b0 dropped (~6e-5 rel)
// MODE: 0=+bias 1=silu(+bias) 2=(+bias)*extra 3=(+bias)+extra
template<int MODE>
__global__ __launch_bounds__(256, 1)
void ig_gemm(const int8_t* __restrict__ A1, const int8_t* __restrict__ A0,
             const int8_t* __restrict__ B1, const int8_t* __restrict__ B0,
             const float* __restrict__ sA, const float* __restrict__ sB,
             const float* __restrict__ bias, const float* __restrict__ extra,
             float* __restrict__ C32,
             const int* __restrict__ counts, int capRows, int N, int K)
{
    const int z  = blockIdx.z;
    const int m0 = blockIdx.y * BM;
    const int n0 = blockIdx.x * BN;
    int cnt = capRows;
    if (counts) { cnt = counts[z]; if (m0 >= cnt) return; }

    extern __shared__ __align__(128) char smem[];
    const uint32_t sb = smem_u32(smem);
    const int tid = threadIdx.x, lane = tid & 31, wid = tid >> 5;
    const int warp_m = wid & 1;        // 2 warps over M (64 rows)
    const int warp_n = wid >> 1;       // 4 warps over N (32 cols)

    const size_t Kb = (size_t)K;       // bytes per digit row
    const long rowA0 = (long)z * capRows + m0;
    const long rowB0 = (long)z * N + n0;
    const int  C = K / KC;

    int acc2[4][4][4], acc1[4][4][4];
#pragma unroll
    for (int i = 0; i < 4; i++)
#pragma unroll
        for (int j = 0; j < 4; j++)
#pragma unroll
            for (int q = 0; q < 4; q++) { acc2[i][j][q] = 0; acc1[i][j][q] = 0; }

    fill_stage(sb, tid, A1, A0, B1, B0, Kb, rowA0, rowB0, 0);
    if (C > 1) fill_stage(sb + STAGE_BYTES, tid, A1, A0, B1, B0, Kb, rowA0, rowB0, KC);

    const int lm = lane & 15;
    const int lkb = (lane >> 4) << 4;

    for (int c = 0; c < C; c++) {
        if (c + 2 < C) asm volatile("cp.async.wait_group 1;" ::: "memory");
        else           asm volatile("cp.async.wait_group 0;" ::: "memory");
        __syncthreads();
        if (c + 2 < C)
            fill_stage(sb + ((c + 2) % NSTAGE) * STAGE_BYTES, tid, A1, A0, B1, B0,
                       Kb, rowA0, rowB0, (size_t)(c + 2) * KC);

        const uint32_t stg = sb + (c % NSTAGE) * STAGE_BYTES;
#pragma unroll
        for (int kk = 0; kk < 2; kk++) {           // 2 x k32 per 64B chunk
            const uint32_t kb = kk * 32 + lkb;
            uint32_t a1f[4][4], a0f[4][4], b1f[2][4], b0f[2][4];
#pragma unroll
            for (int mt = 0; mt < 4; mt++) {
                uint32_t ad = stg + (warp_m * 64 + mt * 16 + lm) * ROWB + kb;
                LDSM4(a1f[mt], ad + OFF_A1);
                LDSM4(a0f[mt], ad + OFF_A0);
            }
#pragma unroll
            for (int nt2 = 0; nt2 < 2; nt2++) {
                uint32_t bd = stg + (warp_n * 32 + nt2 * 16 + lm) * ROWB + kb;
                LDSM4(b1f[nt2], bd + OFF_B1);
                LDSM4(b0f[nt2], bd + OFF_B0);
            }
            // P2: a1*b1 (16 independent MMAs)
#pragma unroll
            for (int mt = 0; mt < 4; mt++)
#pragma unroll
                for (int nt = 0; nt < 4; nt++) {
                    const int n2 = nt >> 1, o = nt & 1;
                    MMA_S8(acc2[mt][nt], a1f[mt], b1f[n2][o], b1f[n2][o + 2]);
                }
            // P1a: a1*b0
#pragma unroll
            for (int mt = 0; mt < 4; mt++)
#pragma unroll
                for (int nt = 0; nt < 4; nt++) {
                    const int n2 = nt >> 1, o = nt & 1;
                    MMA_S8(acc1[mt][nt], a1f[mt], b0f[n2][o], b0f[n2][o + 2]);
                }
            // P1b: a0*b1
#pragma unroll
            for (int mt = 0; mt < 4; mt++)
#pragma unroll
                for (int nt = 0; nt < 4; nt++) {
                    const int n2 = nt >> 1, o = nt & 1;
                    MMA_S8(acc1[mt][nt], a0f[mt], b1f[n2][o], b1f[n2][o + 2]);
                }
        }
    }

    // ---- epilogue ----
    const float* biasz = bias + (size_t)z * N;
    const float* sBz   = sB + (size_t)z * N;
#pragma unroll
    for (int mt = 0; mt < 4; mt++) {
#pragma unroll
        for (int half = 0; half < 2; half++) {
            const int rtile = warp_m * 64 + mt * 16 + (lane >> 2) + half * 8;
            if (m0 + rtile >= cnt) continue;
            const size_t gr = (size_t)z * capRows + m0 + rtile;
            const float sa = sA[gr];
#pragma unroll
            for (int nt = 0; nt < 4; nt++) {
                const int col = n0 + warp_n * 32 + nt * 8 + (lane & 3) * 2;
                const float sb0 = sBz[col], sb1 = sBz[col + 1];
                float p2a = (float)acc2[mt][nt][half * 2 + 0];
                float p2b = (float)acc2[mt][nt][half * 2 + 1];
                float p1a = (float)acc1[mt][nt][half * 2 + 0];
                float p1b = (float)acc1[mt][nt][half * 2 + 1];
                float v0 = sa * sb0 * (C2F * p2a + C1F * p1a) + biasz[col];
                float v1 = sa * sb1 * (C2F * p2b + C1F * p1b) + biasz[col + 1];
                if (MODE == 1) { v0 = silu_f(v0); v1 = silu_f(v1); }
                if (MODE == 2) {
                    const float2 e = *(const float2*)&extra[gr * N + col];
                    v0 *= e.x; v1 *= e.y;
                }
                if (MODE == 3) {
                    const float2 e = *(const float2*)&extra[gr * N + col];
                    v0 += e.x; v1 += e.y;
                }
                float2 w = {v0, v1};
                *(float2*)&C32[gr * N + col] = w;
            }
        }
    }
}

// ---------------- quantization kernels ----------------
// per-row scale + two base-128 digits
__global__ void rowquant_k(const float* __restrict__ in, int8_t* __restrict__ d1,
                           int8_t* __restrict__ d0, float* __restrict__ scale,
                           const int* __restrict__ counts, int K)
{
    const int r = blockIdx.x;
    if (counts) { if ((r & (CAP - 1)) >= counts[r >> 12]) return; }
    const float* row = in + (size_t)r * K;
    float m = 0.f;
    for (int i = threadIdx.x; i < K; i += 256) m = fmaxf(m, fabsf(row[i]));
    __shared__ float red[256];
    red[threadIdx.x] = m;
    __syncthreads();
    for (int s = 128; s > 0; s >>= 1) {
        if (threadIdx.x < s) red[threadIdx.x] = fmaxf(red[threadIdx.x], red[threadIdx.x + s]);
        __syncthreads();
    }
    const float S = red[0];
    const float inv = (S > 0.f) ? QSCL / S : 0.f;
    if (threadIdx.x == 0) scale[r] = S;
    for (int i = threadIdx.x; i < K; i += 256) {
        int q = __float2int_rn(row[i] * inv);
        int a1 = (q + 64) >> 7;
        d1[(size_t)r * K + i] = (int8_t)a1;
        d0[(size_t)r * K + i] = (int8_t)(q - (a1 << 7));
    }
}

// per-column max of W [z, K, N]
__global__ void colmax_k(const float* __restrict__ W, float* __restrict__ smax, int K, int N)
{
    const int n = blockIdx.x * 256 + threadIdx.x;
    const float* Wz = W + (size_t)blockIdx.z * K * N;
    float m = 0.f;
    for (int k = 0; k < K; k++) m = fmaxf(m, fabsf(Wz[(size_t)k * N + n]));
    smax[blockIdx.z * N + n] = m;
}

// transpose + quantize: W [z, K, N] -> digits [(z*N + n), k]
__global__ void convTq_k(const float* __restrict__ W, const float* __restrict__ smax,
                         int8_t* __restrict__ d1, int8_t* __restrict__ d0, int K, int N)
{
    __shared__ float t[32][33];
    const int n0 = blockIdx.x * 32, k0 = blockIdx.y * 32;
    const float* Wz = W + (size_t)blockIdx.z * K * N;
    for (int i = threadIdx.y; i < 32; i += 8)
        t[i][threadIdx.x] = Wz[(size_t)(k0 + i) * N + n0 + threadIdx.x];
    __syncthreads();
    for (int i = threadIdx.y; i < 32; i += 8) {
        const int n = n0 + i;
        const float S = smax[blockIdx.z * N + n];
        const float inv = (S > 0.f) ? QSCL / S : 0.f;
        const size_t o = ((size_t)blockIdx.z * N + n) * K + k0 + threadIdx.x;
        int q = __float2int_rn(t[threadIdx.x][i] * inv);
        int a1 = (q + 64) >> 7;
        d1[o] = (int8_t)a1;
        d0[o] = (int8_t)(q - (a1 << 7));
    }
}

// ---------------- router / pack / combine / head ----------------
__global__ void zero_counts_k(int* counts) { if (threadIdx.x < EE) counts[threadIdx.x] = 0; }

__global__ void router_k(const float* __restrict__ p, const float* __restrict__ Wg,
                         int* __restrict__ counts, int* __restrict__ slot_token,
                         int* __restrict__ pair_slot, float* __restrict__ pair_gate)
{
    const int t = blockIdx.x;
    const int tid = threadIdx.x; // 128
    __shared__ float red[EE][128];
    float acc[EE];
#pragma unroll
    for (int e = 0; e < EE; e++) acc[e] = 0.f;
    const float* pr = p + (size_t)t * PP;
    for (int j = tid; j < PP; j += 128) {
        float pv = pr[j];
        const float* wg = Wg + (size_t)j * EE;
#pragma unroll
        for (int e = 0; e < EE; e++) acc[e] += pv * wg[e];
    }
#pragma unroll
    for (int e = 0; e < EE; e++) red[e][tid] = acc[e];
    __syncthreads();
    if (tid == 0) {
        float logit[EE];
        for (int e = 0; e < EE; e++) {
            float s = 0.f;
            for (int i = 0; i < 128; i++) s += red[e][i];
            logit[e] = s;
        }
        int i0 = 0;
        for (int e = 1; e < EE; e++) if (logit[e] > logit[i0]) i0 = e;
        int i1 = (i0 == 0) ? 1 : 0;
        for (int e = 0; e < EE; e++) {
            if (e == i0) continue;
            if (logit[e] > logit[i1]) i1 = e;
        }
        float g0 = 1.f / (1.f + expf(logit[i1] - logit[i0]));
        float g1 = 1.f - g0;
        int s0 = atomicAdd(&counts[i0], 1);
        int s1 = atomicAdd(&counts[i1], 1);
        slot_token[i0 * CAP + s0] = t;
        slot_token[i1 * CAP + s1] = t;
        pair_slot[2 * t]     = i0 * CAP + s0;
        pair_slot[2 * t + 1] = i1 * CAP + s1;
        pair_gate[2 * t]     = g0;
        pair_gate[2 * t + 1] = g1;
    }
}

// gather p digit rows + scale into per-expert packed layout
__global__ void pack_k(const int8_t* __restrict__ pd1, const int8_t* __restrict__ pd0,
                       const float* __restrict__ sp,
                       const int* __restrict__ stok, const int* __restrict__ counts,
                       int8_t* __restrict__ ad1, int8_t* __restrict__ ad0,
                       float* __restrict__ sap)
{
    const int slot = blockIdx.x;
    if ((slot & (CAP - 1)) >= counts[slot >> 12]) return;
    const int tok = stok[slot];
    const int t = threadIdx.x;   // 128 threads; PP bytes = 64 uint4 per digit
    if (t < 64) {
        ((uint4*)(ad1 + (size_t)slot * PP))[t] = ((const uint4*)(pd1 + (size_t)tok * PP))[t];
    } else {
        ((uint4*)(ad0 + (size_t)slot * PP))[t - 64] = ((const uint4*)(pd0 + (size_t)tok * PP))[t - 64];
    }
    if (t == 0) sap[slot] = sp[tok];
}

__global__ void combine_k(const float* __restrict__ eo, const int* __restrict__ pair_slot,
                          const float* __restrict__ pair_gate, float* __restrict__ moe)
{
    int idx = blockIdx.x * blockDim.x + threadIdx.x;
    if (idx >= B_TOK * PP) return;
    int t = idx >> 10, j = idx & (PP - 1);
    int s0 = pair_slot[2 * t], s1 = pair_slot[2 * t + 1];
    float g0 = pair_gate[2 * t], g1 = pair_gate[2 * t + 1];
    moe[idx] = g0 * eo[(size_t)s0 * PP + j] + g1 * eo[(size_t)s1 * PP + j];
}

__global__ __launch_bounds__(256)
void head_k(const float* __restrict__ hid2, const float* __restrict__ head_w,
            const float* __restrict__ head_b, float* __restrict__ out)
{
    const int t = blockIdx.x, tid = threadIdx.x;
    const int lane = tid & 31, warp = tid >> 5;
    __shared__ float row[HH];
    for (int i = tid; i < HH; i += 256) row[i] = hid2[(size_t)t * HH + i];
    __syncthreads();
#pragma unroll
    for (int oo = 0; oo < 4; oo++) {
        int o = warp + oo * 8;
        if (o >= OUTN) break;
        float s = 0.f;
        for (int i = lane; i < HH; i += 32) s += row[i] * head_w[(size_t)i * OUTN + o];
#pragma unroll
        for (int off = 16; off > 0; off >>= 1) s += __shfl_down_sync(0xFFFFFFFFu, s, off);
        if (lane == 0) out[(size_t)t * OUTN + o] = s + head_b[o];
    }
}

// ---------------- launch ----------------
template <typename T>
static T* symaddr(const void* sym) { void* p = nullptr; cudaGetSymbolAddress(&p, sym); return (T*)p; }

extern "C" void kernel_launch(void* const* d_in, const int* in_sizes, int n_in,
                              void* d_out, int out_size)
{
    const float* x      = (const float*)d_in[0];
    const float* Wproj  = (const float*)d_in[1];
    const float* bproj  = (const float*)d_in[2];
    const float* Wg     = (const float*)d_in[3];
    const float* W1     = (const float*)d_in[4];
    const float* b1     = (const float*)d_in[5];
    const float* W2     = (const float*)d_in[6];
    const float* b2     = (const float*)d_in[7];
    const float* sg_w   = (const float*)d_in[8];
    const float* sg_b   = (const float*)d_in[9];
    const float* su_w   = (const float*)d_in[10];
    const float* su_b   = (const float*)d_in[11];
    const float* sd_w   = (const float*)d_in[12];
    const float* sd_b   = (const float*)d_in[13];
    const float* m1_w   = (const float*)d_in[14];
    const float* m1_b   = (const float*)d_in[15];
    const float* m2_w   = (const float*)d_in[16];
    const float* m2_b   = (const float*)d_in[17];
    const float* head_w = (const float*)d_in[18];
    const float* head_b = (const float*)d_in[19];
    float* out = (float*)d_out;

    static bool attr_done = false;
    if (!attr_done) {
        cudaFuncSetAttribute(ig_gemm<0>, cudaFuncAttributeMaxDynamicSharedMemorySize, SMEM_BYTES);
        cudaFuncSetAttribute(ig_gemm<1>, cudaFuncAttributeMaxDynamicSharedMemorySize, SMEM_BYTES);
        cudaFuncSetAttribute(ig_gemm<2>, cudaFuncAttributeMaxDynamicSharedMemorySize, SMEM_BYTES);
        cudaFuncSetAttribute(ig_gemm<3>, cudaFuncAttributeMaxDynamicSharedMemorySize, SMEM_BYTES);
        attr_done = true;
    }

    int8_t *x1 = symaddr<int8_t>(g_x1), *x0 = symaddr<int8_t>(g_x0);
    float  *sx = symaddr<float>(g_sx);
    float  *p32 = symaddr<float>(g_p32);
    int8_t *p1 = symaddr<int8_t>(g_p1), *p0 = symaddr<int8_t>(g_p0);
    float  *sp = symaddr<float>(g_sp);
    int8_t *ap1 = symaddr<int8_t>(g_ap1), *ap0 = symaddr<int8_t>(g_ap0);
    float  *sap = symaddr<float>(g_sap);
    float  *h32 = symaddr<float>(g_h32);
    int8_t *hq1 = symaddr<int8_t>(g_hq1), *hq0 = symaddr<int8_t>(g_hq0);
    float  *sh = symaddr<float>(g_sh);
    float  *eo32 = symaddr<float>(g_eo32);
    float  *moe = symaddr<float>(g_moe);
    float  *sg32 = symaddr<float>(g_sg32);
    float  *su32 = symaddr<float>(g_su32);
    int8_t *su1 = symaddr<int8_t>(g_su1), *su0 = symaddr<int8_t>(g_su0);
    float  *ssu = symaddr<float>(g_ssu);
    float  *cb32 = symaddr<float>(g_cb32);
    int8_t *cb1 = symaddr<int8_t>(g_cb1), *cb0 = symaddr<int8_t>(g_cb0);
    float  *scb = symaddr<float>(g_scb);
    float  *h132 = symaddr<float>(g_h132);
    int8_t *h11 = symaddr<int8_t>(g_h11), *h10 = symaddr<int8_t>(g_h10);
    float  *sh1 = symaddr<float>(g_sh1);
    float  *h232 = symaddr<float>(g_h232);
    int8_t *wp1 = symaddr<int8_t>(g_wp1), *wp0 = symaddr<int8_t>(g_wp0);
    float  *swp = symaddr<float>(g_swp);
    int8_t *w11 = symaddr<int8_t>(g_w11), *w10 = symaddr<int8_t>(g_w10);
    float  *sw1 = symaddr<float>(g_sw1);
    int8_t *w21 = symaddr<int8_t>(g_w21), *w20 = symaddr<int8_t>(g_w20);
    float  *sw2 = symaddr<float>(g_sw2);
    int8_t *sgw1 = symaddr<int8_t>(g_sgw1), *sgw0 = symaddr<int8_t>(g_sgw0);
    float  *ssgw = symaddr<float>(g_ssgw);
    int8_t *suw1 = symaddr<int8_t>(g_suw1), *suw0 = symaddr<int8_t>(g_suw0);
    float  *ssuw = symaddr<float>(g_ssuw);
    int8_t *sdw1 = symaddr<int8_t>(g_sdw1), *sdw0 = symaddr<int8_t>(g_sdw0);
    float  *ssdw = symaddr<float>(g_ssdw);
    int8_t *m11 = symaddr<int8_t>(g_m11), *m10 = symaddr<int8_t>(g_m10);
    float  *sm1 = symaddr<float>(g_sm1);
    int8_t *m21 = symaddr<int8_t>(g_m21), *m20 = symaddr<int8_t>(g_m20);
    float  *sm2 = symaddr<float>(g_sm2);
    int *counts = symaddr<int>(g_counts);
    int *stok   = symaddr<int>(g_slot_token);
    int *pslot  = symaddr<int>(g_pair_slot);
    float *pgate = symaddr<float>(g_pair_gate);

    // launches 1-5: prep so launch 6 (ncu -s 5 -c 1 capture) is a main GEMM
    colmax_k<<<dim3(PP / 256, 1, 1), 256>>>(Wproj, swp, DIN, PP);                      // 1
    convTq_k<<<dim3(PP / 32, DIN / 32, 1), dim3(32, 8)>>>(Wproj, swp, wp1, wp0, DIN, PP); // 2
    colmax_k<<<dim3(HH / 256, 1, EE), 256>>>(W1, sw1, PP, HH);                          // 3
    convTq_k<<<dim3(HH / 32, PP / 32, EE), dim3(32, 8)>>>(W1, sw1, w11, w10, PP, HH);   // 4
    rowquant_k<<<B_TOK, 256>>>(x, x1, x0, sx, nullptr, DIN);                            // 5
    // 6: p = x @ Wproj + bproj
    ig_gemm<0><<<dim3(PP / BN, B_TOK / BM, 1), 256, SMEM_BYTES>>>(
        x1, x0, wp1, wp0, sx, swp, bproj, nullptr, p32, nullptr, B_TOK, PP, DIN);
    // router + pack
    zero_counts_k<<<1, 32>>>(counts);
    router_k<<<B_TOK, 128>>>(p32, Wg, counts, stok, pslot, pgate);
    rowquant_k<<<B_TOK, 256>>>(p32, p1, p0, sp, nullptr, PP);
    pack_k<<<EE * CAP, 128>>>(p1, p0, sp, stok, counts, ap1, ap0, sap);
    // remaining weight preps
    colmax_k<<<dim3(PP / 256, 1, EE), 256>>>(W2, sw2, HH, PP);
    convTq_k<<<dim3(PP / 32, HH / 32, EE), dim3(32, 8)>>>(W2, sw2, w21, w20, HH, PP);
    colmax_k<<<dim3(HSH / 256, 1, 1), 256>>>(sg_w, ssgw, PP, HSH);
    convTq_k<<<dim3(HSH / 32, PP / 32, 1), dim3(32, 8)>>>(sg_w, ssgw, sgw1, sgw0, PP, HSH);
    colmax_k<<<dim3(HSH / 256, 1, 1), 256>>>(su_w, ssuw, PP, HSH);
    convTq_k<<<dim3(HSH / 32, PP / 32, 1), dim3(32, 8)>>>(su_w, ssuw, suw1, suw0, PP, HSH);
    colmax_k<<<dim3(PP / 256, 1, 1), 256>>>(sd_w, ssdw, HSH, PP);
    convTq_k<<<dim3(PP / 32, HSH / 32, 1), dim3(32, 8)>>>(sd_w, ssdw, sdw1, sdw0, HSH, PP);
    colmax_k<<<dim3(HH / 256, 1, 1), 256>>>(m1_w, sm1, PP, HH);
    convTq_k<<<dim3(HH / 32, PP / 32, 1), dim3(32, 8)>>>(m1_w, sm1, m11, m10, PP, HH);
    colmax_k<<<dim3(HH / 256, 1, 1), 256>>>(m2_w, sm2, HH, HH);
    convTq_k<<<dim3(HH / 32, HH / 32, 1), dim3(32, 8)>>>(m2_w, sm2, m21, m20, HH, HH);
    // expert fc1: h = silu(ap @ W1^T + b1)
    ig_gemm<1><<<dim3(HH / BN, CAP / BM, EE), 256, SMEM_BYTES>>>(
        ap1, ap0, w11, w10, sap, sw1, b1, nullptr, h32, counts, CAP, HH, PP);
    rowquant_k<<<EE * CAP, 256>>>(h32, hq1, hq0, sh, counts, HH);
    // expert fc2: eo = h @ W2^T + b2
    ig_gemm<0><<<dim3(PP / BN, CAP / BM, EE), 256, SMEM_BYTES>>>(
        hq1, hq0, w21, w20, sh, sw2, b2, nullptr, eo32, counts, CAP, PP, HH);
    combine_k<<<(B_TOK * PP + 255) / 256, 256>>>(eo32, pslot, pgate, moe);
    // shared SwiGLU
    ig_gemm<1><<<dim3(HSH / BN, B_TOK / BM, 1), 256, SMEM_BYTES>>>(
        p1, p0, sgw1, sgw0, sp, ssgw, sg_b, nullptr, sg32, nullptr, B_TOK, HSH, PP);
    ig_gemm<2><<<dim3(HSH / BN, B_TOK / BM, 1), 256, SMEM_BYTES>>>(
        p1, p0, suw1, suw0, sp, ssuw, su_b, sg32, su32, nullptr, B_TOK, HSH, PP);
    rowquant_k<<<B_TOK, 256>>>(su32, su1, su0, ssu, nullptr, HSH);
    // down proj + moe residual
    ig_gemm<3><<<dim3(PP / BN, B_TOK / BM, 1), 256, SMEM_BYTES>>>(
        su1, su0, sdw1, sdw0, ssu, ssdw, sd_b, moe, cb32, nullptr, B_TOK, PP, HSH);
    rowquant_k<<<B_TOK, 256>>>(cb32, cb1, cb0, scb, nullptr, PP);
    // output MLP
    ig_gemm<1><<<dim3(HH / BN, B_TOK / BM, 1), 256, SMEM_BYTES>>>(
        cb1, cb0, m11, m10, scb, sm1, m1_b, nullptr, h132, nullptr, B_TOK, HH, PP);
    rowquant_k<<<B_TOK, 256>>>(h132, h11, h10, sh1, nullptr, HH);
    ig_gemm<0><<<dim3(HH / BN, B_TOK / BM, 1), 256, SMEM_BYTES>>>(
        h11, h10, m21, m20, sh1, sm2, m2_b, nullptr, h232, nullptr, B_TOK, HH, HH);
    // head
    head_k<<<B_TOK, 256>>>(h232, head_w, head_b, out);
}

// round 8
// speedup vs baseline: 2.4846x; 2.4846x over previous
#include <cuda_runtime.h>
#include <cuda_bf16.h>
#include <math.h>
#include <stdint.h>

// ---------------- problem constants ----------------
#define B_TOK 4096
#define DIN   512
#define PP    1024
#define HH    2048
#define EE    8
#define HSH   4096
#define OUTN  29
#define CAP   4096

// ---------------- mma.sync GEMM tile config ----------------
#define BM 128
#define BN 256
#define BKC 32                     // bf16 k elems per chunk (64 bytes)
#define ROWB 80                    // smem row stride (64B data + 16B pad)
#define OFF_AH 0
#define OFF_AL (128 * ROWB)
#define OFF_BH (256 * ROWB)
#define OFF_BL (256 * ROWB + 256 * ROWB)
#define STAGE_BYTES (768 * ROWB)   // 61440
#define NSTAGE 3
#define SMEM_BYTES (NSTAGE * STAGE_BYTES) // 184320
#define NTHR 512                   // 16 warps: 4 (M) x 4 (N); warp tile 32x64

// ---------------- PTX helpers ----------------
__device__ __forceinline__ uint32_t smem_u32(const void* p) {
    uint32_t a;
    asm("{ .reg .u64 t; cvta.to.shared.u64 t, %1; cvt.u32.u64 %0, t; }" : "=r"(a) : "l"(p));
    return a;
}
#define CP16(dst, src) asm volatile("cp.async.cg.shared.global [%0], [%1], 16;" :: "r"(dst), "l"(src) : "memory")
#define CP_COMMIT()    asm volatile("cp.async.commit_group;" ::: "memory")

#define LDSM4(r, addr) \
    asm volatile("ldmatrix.sync.aligned.m8n8.x4.shared.b16 {%0,%1,%2,%3}, [%4];" \
        : "=r"((r)[0]), "=r"((r)[1]), "=r"((r)[2]), "=r"((r)[3]) : "r"(addr))

#define MMA_BF16(c, a, b0, b1) \
    asm volatile("mma.sync.aligned.m16n8k16.row.col.f32.bf16.bf16.f32 " \
        "{%0,%1,%2,%3}, {%4,%5,%6,%7}, {%8,%9}, {%0,%1,%2,%3};" \
        : "+f"((c)[0]), "+f"((c)[1]), "+f"((c)[2]), "+f"((c)[3]) \
        : "r"((a)[0]), "r"((a)[1]), "r"((a)[2]), "r"((a)[3]), "r"(b0), "r"(b1))

// ---------------- scratch (device globals) ----------------
#define DEV __device__ __align__(128)
DEV __nv_bfloat16 g_x_hi [B_TOK * DIN],   g_x_lo [B_TOK * DIN];
DEV __nv_bfloat16 g_p_hi [B_TOK * PP],    g_p_lo [B_TOK * PP];
DEV float         g_p32  [B_TOK * PP];
DEV __nv_bfloat16 g_ap_hi[EE * CAP * PP], g_ap_lo[EE * CAP * PP];
DEV __nv_bfloat16 g_h_hi [(size_t)EE * CAP * HH], g_h_lo [(size_t)EE * CAP * HH];
DEV float         g_eo32 [(size_t)EE * CAP * PP];
DEV float         g_moe  [B_TOK * PP];
DEV float         g_sg32 [(size_t)B_TOK * HSH];
DEV __nv_bfloat16 g_su_hi[(size_t)B_TOK * HSH],   g_su_lo[(size_t)B_TOK * HSH];
DEV __nv_bfloat16 g_cb_hi[B_TOK * PP],    g_cb_lo[B_TOK * PP];
DEV __nv_bfloat16 g_h1_hi[B_TOK * HH],    g_h1_lo[B_TOK * HH];
DEV float         g_h232 [B_TOK * HH];
DEV __nv_bfloat16 g_wp_hi [PP * DIN],     g_wp_lo [PP * DIN];
DEV __nv_bfloat16 g_w1_hi [EE * HH * PP], g_w1_lo [EE * HH * PP];
DEV __nv_bfloat16 g_w2_hi [EE * PP * HH], g_w2_lo [EE * PP * HH];
DEV __nv_bfloat16 g_sgw_hi[HSH * PP],     g_sgw_lo[HSH * PP];
DEV __nv_bfloat16 g_suw_hi[HSH * PP],     g_suw_lo[HSH * PP];
DEV __nv_bfloat16 g_sdw_hi[PP * HSH],     g_sdw_lo[PP * HSH];
DEV __nv_bfloat16 g_m1_hi [HH * PP],      g_m1_lo [HH * PP];
DEV __nv_bfloat16 g_m2_hi [HH * HH],      g_m2_lo [HH * HH];
DEV int   g_counts[EE];
DEV int   g_slot_token[EE * CAP];
DEV int   g_pair_slot[B_TOK * 2];
DEV float g_pair_gate[B_TOK * 2];

__device__ __forceinline__ float silu_f(float x) { return x / (1.0f + expf(-x)); }

// ---------------- stage fill (512 threads): A 128 rows + B 256 rows, hi+lo ----------------
__device__ __forceinline__ void fill_stage(uint32_t st, int tid,
    const char* Ah, const char* Al, const char* Bh, const char* Bl,
    size_t Kb, long rowA0, long rowB0, size_t kByte)
{
    {   // A: 128 rows x 4 x 16B = 512 assignments
        int row = tid >> 2, ch = tid & 3;
        uint32_t d = st + row * ROWB + ch * 16;
        size_t s = (size_t)(rowA0 + row) * Kb + kByte + ch * 16;
        CP16(d + OFF_AH, Ah + s);
        CP16(d + OFF_AL, Al + s);
    }
#pragma unroll
    for (int i = 0; i < 2; i++) {   // B: 256 rows x 4 x 16B
        int p = tid + (i << 9);
        int row = p >> 2, ch = p & 3;
        uint32_t d = st + row * ROWB + ch * 16;
        size_t s = (size_t)(rowB0 + row) * Kb + kByte + ch * 16;
        CP16(d + OFF_BH, Bh + s);
        CP16(d + OFF_BL, Bl + s);
    }
    CP_COMMIT();
}

// ---------------- bf16-split x3 GEMM, 16 warps, warp tile 32x64 ----------------
// MODE: 0=+bias 1=silu(+bias) 2=(+bias)*extra 3=(+bias)+extra
template<int MODE>
__global__ __launch_bounds__(NTHR, 1)
void mm_gemm(const __nv_bfloat16* __restrict__ Ahi, const __nv_bfloat16* __restrict__ Alo,
             const __nv_bfloat16* __restrict__ Bhi, const __nv_bfloat16* __restrict__ Blo,
             const float* __restrict__ bias, const float* __restrict__ extra,
             float* __restrict__ C32, __nv_bfloat16* __restrict__ Chi,
             __nv_bfloat16* __restrict__ Clo,
             const int* __restrict__ counts, int capRows, int N, int K)
{
    const int z  = blockIdx.z;
    const int m0 = blockIdx.y * BM;
    const int n0 = blockIdx.x * BN;
    int cnt = capRows;
    if (counts) { cnt = counts[z]; if (m0 >= cnt) return; }

    extern __shared__ __align__(128) char smem[];
    const uint32_t sb = smem_u32(smem);
    const int tid = threadIdx.x, lane = tid & 31, wid = tid >> 5;
    const int warp_m = wid & 3;        // 4 warps over M (32 rows each)
    const int warp_n = wid >> 2;       // 4 warps over N (64 cols each)

    const size_t Kb = (size_t)K * 2;
    const long rowA0 = (long)z * capRows + m0;
    const long rowB0 = (long)z * N + n0;
    const int  C = K / BKC;

    float acc[2][8][4];
#pragma unroll
    for (int i = 0; i < 2; i++)
#pragma unroll
        for (int j = 0; j < 8; j++)
#pragma unroll
            for (int q = 0; q < 4; q++) acc[i][j][q] = 0.f;

    const char* Ah = (const char*)Ahi; const char* Al = (const char*)Alo;
    const char* Bh = (const char*)Bhi; const char* Bl = (const char*)Blo;

    fill_stage(sb, tid, Ah, Al, Bh, Bl, Kb, rowA0, rowB0, 0);
    if (C > 1) fill_stage(sb + STAGE_BYTES, tid, Ah, Al, Bh, Bl, Kb, rowA0, rowB0, 64);

    const int lm = lane & 15;
    const int lkb = (lane >> 4) << 4;

    for (int c = 0; c < C; c++) {
        if (c + 2 < C) asm volatile("cp.async.wait_group 1;" ::: "memory");
        else           asm volatile("cp.async.wait_group 0;" ::: "memory");
        __syncthreads();
        if (c + 2 < C)
            fill_stage(sb + ((c + 2) % NSTAGE) * STAGE_BYTES, tid, Ah, Al, Bh, Bl,
                       Kb, rowA0, rowB0, (size_t)(c + 2) * 64);

        const uint32_t stg = sb + (c % NSTAGE) * STAGE_BYTES;
#pragma unroll
        for (int kk = 0; kk < 2; kk++) {
            const uint32_t kb = kk * 32 + lkb;
            uint32_t a_h[2][4], a_l[2][4];
#pragma unroll
            for (int mt = 0; mt < 2; mt++) {
                uint32_t ad = stg + (warp_m * 32 + mt * 16 + lm) * ROWB + kb;
                LDSM4(a_h[mt], ad + OFF_AH);
                LDSM4(a_l[mt], ad + OFF_AL);
            }
#pragma unroll
            for (int n2 = 0; n2 < 4; n2++) {
                uint32_t b_h[4], b_l[4];
                uint32_t bd = stg + (warp_n * 64 + n2 * 16 + lm) * ROWB + kb;
                LDSM4(b_h, bd + OFF_BH);
                LDSM4(b_l, bd + OFF_BL);
#pragma unroll
                for (int mt = 0; mt < 2; mt++)
#pragma unroll
                    for (int o = 0; o < 2; o++) {
                        const int nt = n2 * 2 + o;
                        MMA_BF16(acc[mt][nt], a_h[mt], b_h[o], b_h[o + 2]);
                        MMA_BF16(acc[mt][nt], a_h[mt], b_l[o], b_l[o + 2]);
                        MMA_BF16(acc[mt][nt], a_l[mt], b_h[o], b_h[o + 2]);
                    }
            }
        }
    }

    // ---- epilogue: registers -> gmem ----
    const float* biasz = bias + (size_t)z * N;
#pragma unroll
    for (int mt = 0; mt < 2; mt++) {
#pragma unroll
        for (int half = 0; half < 2; half++) {
            const int rtile = warp_m * 32 + mt * 16 + (lane >> 2) + half * 8;
            if (m0 + rtile >= cnt) continue;
            const size_t gr = (size_t)z * capRows + m0 + rtile;
#pragma unroll
            for (int nt = 0; nt < 8; nt++) {
                const int col = n0 + warp_n * 64 + nt * 8 + (lane & 3) * 2;
                float v0 = acc[mt][nt][half * 2 + 0] + biasz[col];
                float v1 = acc[mt][nt][half * 2 + 1] + biasz[col + 1];
                if (MODE == 1) { v0 = silu_f(v0); v1 = silu_f(v1); }
                if (MODE == 2) {
                    const float2 e = *(const float2*)&extra[gr * N + col];
                    v0 *= e.x; v1 *= e.y;
                }
                if (MODE == 3) {
                    const float2 e = *(const float2*)&extra[gr * N + col];
                    v0 += e.x; v1 += e.y;
                }
                if (C32) { float2 w = {v0, v1}; *(float2*)&C32[gr * N + col] = w; }
                if (Chi) {
                    __nv_bfloat16 h0 = __float2bfloat16(v0);
                    __nv_bfloat16 h1 = __float2bfloat16(v1);
                    __nv_bfloat162 hp; hp.x = h0; hp.y = h1;
                    *(__nv_bfloat162*)&Chi[gr * N + col] = hp;
                    __nv_bfloat162 lp;
                    lp.x = __float2bfloat16(v0 - __bfloat162float(h0));
                    lp.y = __float2bfloat16(v1 - __bfloat162float(h1));
                    *(__nv_bfloat162*)&Clo[gr * N + col] = lp;
                }
            }
        }
    }
}

// ---------------- small kernels ----------------
__global__ void conv_split_k(const float* __restrict__ in, __nv_bfloat16* __restrict__ hi,
                             __nv_bfloat16* __restrict__ lo, size_t n)
{
    size_t i = (size_t)blockIdx.x * blockDim.x + threadIdx.x;
    if (i >= n) return;
    float v = in[i];
    __nv_bfloat16 h = __float2bfloat16(v);
    hi[i] = h;
    lo[i] = __float2bfloat16(v - __bfloat162float(h));
}

// W [z, K, N] row-major -> out [(z*N + n), k]  (transpose + split)
__global__ void convT_k(const float* __restrict__ W, __nv_bfloat16* __restrict__ hi,
                        __nv_bfloat16* __restrict__ lo, int K, int N)
{
    __shared__ float t[32][33];
    const int n0 = blockIdx.x * 32, k0 = blockIdx.y * 32;
    const float* Wz = W + (size_t)blockIdx.z * K * N;
    for (int i = threadIdx.y; i < 32; i += 8)
        t[i][threadIdx.x] = Wz[(size_t)(k0 + i) * N + n0 + threadIdx.x];
    __syncthreads();
    for (int i = threadIdx.y; i < 32; i += 8) {
        size_t o = ((size_t)blockIdx.z * N + n0 + i) * K + k0 + threadIdx.x;
        float v = t[threadIdx.x][i];
        __nv_bfloat16 h = __float2bfloat16(v);
        hi[o] = h;
        lo[o] = __float2bfloat16(v - __bfloat162float(h));
    }
}

__global__ void zero_counts_k(int* counts) { if (threadIdx.x < EE) counts[threadIdx.x] = 0; }

__global__ void router_k(const float* __restrict__ p, const float* __restrict__ Wg,
                         int* __restrict__ counts, int* __restrict__ slot_token,
                         int* __restrict__ pair_slot, float* __restrict__ pair_gate)
{
    const int t = blockIdx.x;
    const int tid = threadIdx.x; // 128
    __shared__ float red[EE][128];
    float acc[EE];
#pragma unroll
    for (int e = 0; e < EE; e++) acc[e] = 0.f;
    const float* pr = p + (size_t)t * PP;
    for (int j = tid; j < PP; j += 128) {
        float pv = pr[j];
        const float* wg = Wg + (size_t)j * EE;
#pragma unroll
        for (int e = 0; e < EE; e++) acc[e] += pv * wg[e];
    }
#pragma unroll
    for (int e = 0; e < EE; e++) red[e][tid] = acc[e];
    __syncthreads();
    if (tid == 0) {
        float logit[EE];
        for (int e = 0; e < EE; e++) {
            float s = 0.f;
            for (int i = 0; i < 128; i++) s += red[e][i];
            logit[e] = s;
        }
        int i0 = 0;
        for (int e = 1; e < EE; e++) if (logit[e] > logit[i0]) i0 = e;
        int i1 = (i0 == 0) ? 1 : 0;
        for (int e = 0; e < EE; e++) {
            if (e == i0) continue;
            if (logit[e] > logit[i1]) i1 = e;
        }
        float g0 = 1.f / (1.f + expf(logit[i1] - logit[i0]));
        float g1 = 1.f - g0;
        int s0 = atomicAdd(&counts[i0], 1);
        int s1 = atomicAdd(&counts[i1], 1);
        slot_token[i0 * CAP + s0] = t;
        slot_token[i1 * CAP + s1] = t;
        pair_slot[2 * t]     = i0 * CAP + s0;
        pair_slot[2 * t + 1] = i1 * CAP + s1;
        pair_gate[2 * t]     = g0;
        pair_gate[2 * t + 1] = g1;
    }
}

__global__ void pack_k(const __nv_bfloat16* __restrict__ ph, const __nv_bfloat16* __restrict__ pl,
                       const int* __restrict__ stok, const int* __restrict__ counts,
                       __nv_bfloat16* __restrict__ aph, __nv_bfloat16* __restrict__ apl)
{
    const int slot = blockIdx.x;
    const int e = slot >> 12;
    if ((slot & (CAP - 1)) >= counts[e]) return;
    const int tok = stok[slot];
    const float4* s1 = (const float4*)(ph + (size_t)tok * PP);
    const float4* s2 = (const float4*)(pl + (size_t)tok * PP);
    float4* d1 = (float4*)(aph + (size_t)slot * PP);
    float4* d2 = (float4*)(apl + (size_t)slot * PP);
    const int t = threadIdx.x;
    d1[t] = s1[t];
    d2[t] = s2[t];
}

__global__ void combine_k(const float* __restrict__ eo, const int* __restrict__ pair_slot,
                          const float* __restrict__ pair_gate, float* __restrict__ moe)
{
    int idx = blockIdx.x * blockDim.x + threadIdx.x;
    if (idx >= B_TOK * PP) return;
    int t = idx >> 10, j = idx & (PP - 1);
    int s0 = pair_slot[2 * t], s1 = pair_slot[2 * t + 1];
    float g0 = pair_gate[2 * t], g1 = pair_gate[2 * t + 1];
    moe[idx] = g0 * eo[(size_t)s0 * PP + j] + g1 * eo[(size_t)s1 * PP + j];
}

__global__ __launch_bounds__(256)
void head_k(const float* __restrict__ hid2, const float* __restrict__ head_w,
            const float* __restrict__ head_b, float* __restrict__ out)
{
    const int t = blockIdx.x, tid = threadIdx.x;
    const int lane = tid & 31, warp = tid >> 5;
    __shared__ float row[HH];
    for (int i = tid; i < HH; i += 256) row[i] = hid2[(size_t)t * HH + i];
    __syncthreads();
#pragma unroll
    for (int oo = 0; oo < 4; oo++) {
        int o = warp + oo * 8;
        if (o >= OUTN) break;
        float s = 0.f;
        for (int i = lane; i < HH; i += 32) s += row[i] * head_w[(size_t)i * OUTN + o];
#pragma unroll
        for (int off = 16; off > 0; off >>= 1) s += __shfl_down_sync(0xFFFFFFFFu, s, off);
        if (lane == 0) out[(size_t)t * OUTN + o] = s + head_b[o];
    }
}

// ---------------- launch ----------------
template <typename T>
static T* symaddr(const void* sym) { void* p = nullptr; cudaGetSymbolAddress(&p, sym); return (T*)p; }

extern "C" void kernel_launch(void* const* d_in, const int* in_sizes, int n_in,
                              void* d_out, int out_size)
{
    const float* x      = (const float*)d_in[0];
    const float* Wproj  = (const float*)d_in[1];
    const float* bproj  = (const float*)d_in[2];
    const float* Wg     = (const float*)d_in[3];
    const float* W1     = (const float*)d_in[4];
    const float* b1     = (const float*)d_in[5];
    const float* W2     = (const float*)d_in[6];
    const float* b2     = (const float*)d_in[7];
    const float* sg_w   = (const float*)d_in[8];
    const float* sg_b   = (const float*)d_in[9];
    const float* su_w   = (const float*)d_in[10];
    const float* su_b   = (const float*)d_in[11];
    const float* sd_w   = (const float*)d_in[12];
    const float* sd_b   = (const float*)d_in[13];
    const float* m1_w   = (const float*)d_in[14];
    const float* m1_b   = (const float*)d_in[15];
    const float* m2_w   = (const float*)d_in[16];
    const float* m2_b   = (const float*)d_in[17];
    const float* head_w = (const float*)d_in[18];
    const float* head_b = (const float*)d_in[19];
    float* out = (float*)d_out;

    static bool attr_done = false;
    if (!attr_done) {
        cudaFuncSetAttribute(mm_gemm<0>, cudaFuncAttributeMaxDynamicSharedMemorySize, SMEM_BYTES);
        cudaFuncSetAttribute(mm_gemm<1>, cudaFuncAttributeMaxDynamicSharedMemorySize, SMEM_BYTES);
        cudaFuncSetAttribute(mm_gemm<2>, cudaFuncAttributeMaxDynamicSharedMemorySize, SMEM_BYTES);
        cudaFuncSetAttribute(mm_gemm<3>, cudaFuncAttributeMaxDynamicSharedMemorySize, SMEM_BYTES);
        attr_done = true;
    }

    __nv_bfloat16 *x_hi = symaddr<__nv_bfloat16>(g_x_hi),  *x_lo = symaddr<__nv_bfloat16>(g_x_lo);
    __nv_bfloat16 *p_hi = symaddr<__nv_bfloat16>(g_p_hi),  *p_lo = symaddr<__nv_bfloat16>(g_p_lo);
    float *p32  = symaddr<float>(g_p32);
    __nv_bfloat16 *ap_hi = symaddr<__nv_bfloat16>(g_ap_hi), *ap_lo = symaddr<__nv_bfloat16>(g_ap_lo);
    __nv_bfloat16 *h_hi  = symaddr<__nv_bfloat16>(g_h_hi),  *h_lo  = symaddr<__nv_bfloat16>(g_h_lo);
    float *eo32 = symaddr<float>(g_eo32);
    float *moe  = symaddr<float>(g_moe);
    float *sg32 = symaddr<float>(g_sg32);
    __nv_bfloat16 *su_hi = symaddr<__nv_bfloat16>(g_su_hi), *su_lo = symaddr<__nv_bfloat16>(g_su_lo);
    __nv_bfloat16 *cb_hi = symaddr<__nv_bfloat16>(g_cb_hi), *cb_lo = symaddr<__nv_bfloat16>(g_cb_lo);
    __nv_bfloat16 *h1_hi = symaddr<__nv_bfloat16>(g_h1_hi), *h1_lo = symaddr<__nv_bfloat16>(g_h1_lo);
    float *h232 = symaddr<float>(g_h232);
    __nv_bfloat16 *wp_hi = symaddr<__nv_bfloat16>(g_wp_hi), *wp_lo = symaddr<__nv_bfloat16>(g_wp_lo);
    __nv_bfloat16 *w1_hi = symaddr<__nv_bfloat16>(g_w1_hi), *w1_lo = symaddr<__nv_bfloat16>(g_w1_lo);
    __nv_bfloat16 *w2_hi = symaddr<__nv_bfloat16>(g_w2_hi), *w2_lo = symaddr<__nv_bfloat16>(g_w2_lo);
    __nv_bfloat16 *sgw_hi = symaddr<__nv_bfloat16>(g_sgw_hi), *sgw_lo = symaddr<__nv_bfloat16>(g_sgw_lo);
    __nv_bfloat16 *suw_hi = symaddr<__nv_bfloat16>(g_suw_hi), *suw_lo = symaddr<__nv_bfloat16>(g_suw_lo);
    __nv_bfloat16 *sdw_hi = symaddr<__nv_bfloat16>(g_sdw_hi), *sdw_lo = symaddr<__nv_bfloat16>(g_sdw_lo);
    __nv_bfloat16 *m1_hi = symaddr<__nv_bfloat16>(g_m1_hi), *m1_lo = symaddr<__nv_bfloat16>(g_m1_lo);
    __nv_bfloat16 *m2_hi = symaddr<__nv_bfloat16>(g_m2_hi), *m2_lo = symaddr<__nv_bfloat16>(g_m2_lo);
    int *counts = symaddr<int>(g_counts);
    int *stok   = symaddr<int>(g_slot_token);
    int *pslot  = symaddr<int>(g_pair_slot);
    float *pgate = symaddr<float>(g_pair_gate);

    // ---- split inputs / transpose+split weights ----
    conv_split_k<<<(B_TOK * DIN + 255) / 256, 256>>>(x, x_hi, x_lo, (size_t)B_TOK * DIN);
    convT_k<<<dim3(PP / 32, DIN / 32, 1),  dim3(32, 8)>>>(Wproj, wp_hi, wp_lo, DIN, PP);
    convT_k<<<dim3(HH / 32, PP / 32, EE),  dim3(32, 8)>>>(W1, w1_hi, w1_lo, PP, HH);
    convT_k<<<dim3(PP / 32, HH / 32, EE),  dim3(32, 8)>>>(W2, w2_hi, w2_lo, HH, PP);
    convT_k<<<dim3(HSH / 32, PP / 32, 1),  dim3(32, 8)>>>(sg_w, sgw_hi, sgw_lo, PP, HSH);
    convT_k<<<dim3(HSH / 32, PP / 32, 1),  dim3(32, 8)>>>(su_w, suw_hi, suw_lo, PP, HSH);
    convT_k<<<dim3(PP / 32, HSH / 32, 1),  dim3(32, 8)>>>(sd_w, sdw_hi, sdw_lo, HSH, PP);
    convT_k<<<dim3(HH / 32, PP / 32, 1),   dim3(32, 8)>>>(m1_w, m1_hi, m1_lo, PP, HH);
    convT_k<<<dim3(HH / 32, HH / 32, 1),   dim3(32, 8)>>>(m2_w, m2_hi, m2_lo, HH, HH);

    // 1. p = x @ Wproj + bproj
    mm_gemm<0><<<dim3(PP / BN, B_TOK / BM, 1), NTHR, SMEM_BYTES>>>(
        x_hi, x_lo, wp_hi, wp_lo, bproj, nullptr, p32, p_hi, p_lo,
        nullptr, B_TOK, PP, DIN);
    // 2. router + pack
    zero_counts_k<<<1, 32>>>(counts);
    router_k<<<B_TOK, 128>>>(p32, Wg, counts, stok, pslot, pgate);
    pack_k<<<EE * CAP, 128>>>(p_hi, p_lo, stok, counts, ap_hi, ap_lo);
    // 3. expert fc1
    mm_gemm<1><<<dim3(HH / BN, CAP / BM, EE), NTHR, SMEM_BYTES>>>(
        ap_hi, ap_lo, w1_hi, w1_lo, b1, nullptr, nullptr, h_hi, h_lo,
        counts, CAP, HH, PP);
    // 4. expert fc2
    mm_gemm<0><<<dim3(PP / BN, CAP / BM, EE), NTHR, SMEM_BYTES>>>(
        h_hi, h_lo, w2_hi, w2_lo, b2, nullptr, eo32, nullptr, nullptr,
        counts, CAP, PP, HH);
    // 5. combine
    combine_k<<<(B_TOK * PP + 255) / 256, 256>>>(eo32, pslot, pgate, moe);
    // 6. shared SwiGLU
    mm_gemm<1><<<dim3(HSH / BN, B_TOK / BM, 1), NTHR, SMEM_BYTES>>>(
        p_hi, p_lo, sgw_hi, sgw_lo, sg_b, nullptr, sg32, nullptr, nullptr,
        nullptr, B_TOK, HSH, PP);
    mm_gemm<2><<<dim3(HSH / BN, B_TOK / BM, 1), NTHR, SMEM_BYTES>>>(
        p_hi, p_lo, suw_hi, suw_lo, su_b, sg32, nullptr, su_hi, su_lo,
        nullptr, B_TOK, HSH, PP);
    // 7. down proj + moe residual
    mm_gemm<3><<<dim3(PP / BN, B_TOK / BM, 1), NTHR, SMEM_BYTES>>>(
        su_hi, su_lo, sdw_hi, sdw_lo, sd_b, moe, nullptr, cb_hi, cb_lo,
        nullptr, B_TOK, PP, HSH);
    // 8. output MLP
    mm_gemm<1><<<dim3(HH / BN, B_TOK / BM, 1), NTHR, SMEM_BYTES>>>(
        cb_hi, cb_lo, m1_hi, m1_lo, m1_b, nullptr, nullptr, h1_hi, h1_lo,
        nullptr, B_TOK, HH, PP);
    mm_gemm<0><<<dim3(HH / BN, B_TOK / BM, 1), NTHR, SMEM_BYTES>>>(
        h1_hi, h1_lo, m2_hi, m2_lo, m2_b, nullptr, h232, nullptr, nullptr,
        nullptr, B_TOK, HH, HH);
    // 9. head
    head_k<<<B_TOK, 256>>>(h232, head_w, head_b, out);
}

// round 10
// speedup vs baseline: 2.8803x; 1.1593x over previous
#include <cuda_runtime.h>
#include <cuda_bf16.h>
#include <math.h>
#include <stdint.h>

// ---------------- problem constants ----------------
#define B_TOK 4096
#define DIN   512
#define PP    1024
#define HH    2048
#define EE    8
#define HSH   4096
#define OUTN  29
#define CAP   4096

// ---------------- mma.sync GEMM tile config (r8, proven) ----------------
#define BM 128
#define BN 256
#define BKC 32                     // bf16 k elems per chunk (64 bytes)
#define ROWB 80                    // smem row stride (64B data + 16B pad)
#define OFF_AH 0
#define OFF_AL (128 * ROWB)
#define OFF_BH (256 * ROWB)
#define OFF_BL (256 * ROWB + 256 * ROWB)
#define STAGE_BYTES (768 * ROWB)   // 61440
#define NSTAGE 3
#define SMEM_BYTES (NSTAGE * STAGE_BYTES) // 184320
#define NTHR 512                   // 16 warps: 4 (M) x 4 (N); warp tile 32x64

// ---------------- PTX helpers ----------------
__device__ __forceinline__ uint32_t smem_u32(const void* p) {
    uint32_t a;
    asm("{ .reg .u64 t; cvta.to.shared.u64 t, %1; cvt.u32.u64 %0, t; }" : "=r"(a) : "l"(p));
    return a;
}
#define CP16(dst, src) asm volatile("cp.async.cg.shared.global [%0], [%1], 16;" :: "r"(dst), "l"(src) : "memory")
#define CP_COMMIT()    asm volatile("cp.async.commit_group;" ::: "memory")

#define LDSM4(r, addr) \
    asm volatile("ldmatrix.sync.aligned.m8n8.x4.shared.b16 {%0,%1,%2,%3}, [%4];" \
        : "=r"((r)[0]), "=r"((r)[1]), "=r"((r)[2]), "=r"((r)[3]) : "r"(addr))

#define MMA_BF16(c, a, b0, b1) \
    asm volatile("mma.sync.aligned.m16n8k16.row.col.f32.bf16.bf16.f32 " \
        "{%0,%1,%2,%3}, {%4,%5,%6,%7}, {%8,%9}, {%0,%1,%2,%3};" \
        : "+f"((c)[0]), "+f"((c)[1]), "+f"((c)[2]), "+f"((c)[3]) \
        : "r"((a)[0]), "r"((a)[1]), "r"((a)[2]), "r"((a)[3]), "r"(b0), "r"(b1))

// ---------------- scratch (device globals) ----------------
#define DEV __device__ __align__(128)
DEV __nv_bfloat16 g_x_hi [B_TOK * DIN],   g_x_lo [B_TOK * DIN];
DEV __nv_bfloat16 g_p_hi [B_TOK * PP],    g_p_lo [B_TOK * PP];
DEV float         g_p32  [B_TOK * PP];
DEV __nv_bfloat16 g_h_hi [(size_t)EE * CAP * HH], g_h_lo [(size_t)EE * CAP * HH];
DEV float         g_eo32 [(size_t)EE * CAP * PP];
DEV float         g_moe  [B_TOK * PP];
DEV float         g_sg32 [(size_t)B_TOK * HSH];
DEV __nv_bfloat16 g_su_hi[(size_t)B_TOK * HSH],   g_su_lo[(size_t)B_TOK * HSH];
DEV __nv_bfloat16 g_cb_hi[B_TOK * PP],    g_cb_lo[B_TOK * PP];
DEV __nv_bfloat16 g_h1_hi[B_TOK * HH],    g_h1_lo[B_TOK * HH];
DEV float         g_h232 [B_TOK * HH];
DEV __nv_bfloat16 g_wp_hi [PP * DIN],     g_wp_lo [PP * DIN];
DEV __nv_bfloat16 g_w1_hi [EE * HH * PP], g_w1_lo [EE * HH * PP];
DEV __nv_bfloat16 g_w2_hi [EE * PP * HH], g_w2_lo [EE * PP * HH];
DEV __nv_bfloat16 g_sgw_hi[HSH * PP],     g_sgw_lo[HSH * PP];
DEV __nv_bfloat16 g_suw_hi[HSH * PP],     g_suw_lo[HSH * PP];
DEV __nv_bfloat16 g_sdw_hi[PP * HSH],     g_sdw_lo[PP * HSH];
DEV __nv_bfloat16 g_m1_hi [HH * PP],      g_m1_lo [HH * PP];
DEV __nv_bfloat16 g_m2_hi [HH * HH],      g_m2_lo [HH * HH];
DEV int   g_counts[EE];
DEV int   g_slot_token[EE * CAP];
DEV int   g_pair_slot[B_TOK * 2];
DEV float g_pair_gate[B_TOK * 2];

__device__ __forceinline__ float silu_f(float x) { return x / (1.0f + expf(-x)); }

// ---------------- stage fill (512 threads): A 128 rows + B 256 rows, hi+lo ----------------
// GATHER: A row index comes from tokRow[] (fused expert pack)
template<bool GATHER>
__device__ __forceinline__ void fill_stage(uint32_t st, int tid,
    const char* Ah, const char* Al, const char* Bh, const char* Bl,
    size_t Kb, long rowA0, long rowB0, const int* __restrict__ tokRow, size_t kByte)
{
    {   // A: 128 rows x 4 x 16B = 512 slots, both digits
        int row = tid >> 2, ch = tid & 3;
        uint32_t d = st + row * ROWB + ch * 16;
        long arow = GATHER ? (long)tokRow[row] : (rowA0 + row);
        size_t s = (size_t)arow * Kb + kByte + ch * 16;
        CP16(d + OFF_AH, Ah + s);
        CP16(d + OFF_AL, Al + s);
    }
#pragma unroll
    for (int i = 0; i < 2; i++) {   // B: 256 rows x 4 x 16B
        int p = tid + (i << 9);
        int row = p >> 2, ch = p & 3;
        uint32_t d = st + row * ROWB + ch * 16;
        size_t s = (size_t)(rowB0 + row) * Kb + kByte + ch * 16;
        CP16(d + OFF_BH, Bh + s);
        CP16(d + OFF_BL, Bl + s);
    }
    CP_COMMIT();
}

// ---------------- bf16-split x3 GEMM, 16 warps, warp tile 32x64 ----------------
// MODE: 0=+bias 1=silu(+bias) 2=(+bias)*extra 3=(+bias)+extra
template<int MODE, bool GATHER>
__global__ __launch_bounds__(NTHR, 1)
void mm_gemm(const __nv_bfloat16* __restrict__ Ahi, const __nv_bfloat16* __restrict__ Alo,
             const __nv_bfloat16* __restrict__ Bhi, const __nv_bfloat16* __restrict__ Blo,
             const float* __restrict__ bias, const float* __restrict__ extra,
             float* __restrict__ C32, __nv_bfloat16* __restrict__ Chi,
             __nv_bfloat16* __restrict__ Clo,
             const int* __restrict__ counts, const int* __restrict__ stok,
             int capRows, int N, int K)
{
    const int z  = blockIdx.z;
    const int m0 = blockIdx.y * BM;
    const int n0 = blockIdx.x * BN;
    int cnt = capRows;
    if (counts) { cnt = counts[z]; if (m0 >= cnt) return; }

    extern __shared__ __align__(128) char smem[];
    const uint32_t sb = smem_u32(smem);
    const int tid = threadIdx.x, lane = tid & 31, wid = tid >> 5;
    const int warp_m = wid & 3;        // 4 warps over M (32 rows each)
    const int warp_n = wid >> 2;       // 4 warps over N (64 cols each)

    const size_t Kb = (size_t)K * 2;
    const long rowA0 = (long)z * capRows + m0;
    const long rowB0 = (long)z * N + n0;
    const int* tokRow = GATHER ? (stok + z * CAP + m0) : nullptr;
    const int  C = K / BKC;

    float acc[2][8][4];
#pragma unroll
    for (int i = 0; i < 2; i++)
#pragma unroll
        for (int j = 0; j < 8; j++)
#pragma unroll
            for (int q = 0; q < 4; q++) acc[i][j][q] = 0.f;

    const char* Ah = (const char*)Ahi; const char* Al = (const char*)Alo;
    const char* Bh = (const char*)Bhi; const char* Bl = (const char*)Blo;

    fill_stage<GATHER>(sb, tid, Ah, Al, Bh, Bl, Kb, rowA0, rowB0, tokRow, 0);
    if (C > 1) fill_stage<GATHER>(sb + STAGE_BYTES, tid, Ah, Al, Bh, Bl, Kb, rowA0, rowB0, tokRow, 64);

    const int lm = lane & 15;
    const int lkb = (lane >> 4) << 4;

    for (int c = 0; c < C; c++) {
        if (c + 2 < C) asm volatile("cp.async.wait_group 1;" ::: "memory");
        else           asm volatile("cp.async.wait_group 0;" ::: "memory");
        __syncthreads();
        if (c + 2 < C)
            fill_stage<GATHER>(sb + ((c + 2) % NSTAGE) * STAGE_BYTES, tid, Ah, Al, Bh, Bl,
                               Kb, rowA0, rowB0, tokRow, (size_t)(c + 2) * 64);

        const uint32_t stg = sb + (c % NSTAGE) * STAGE_BYTES;
#pragma unroll
        for (int kk = 0; kk < 2; kk++) {
            const uint32_t kb = kk * 32 + lkb;
            uint32_t a_h[2][4], a_l[2][4];
#pragma unroll
            for (int mt = 0; mt < 2; mt++) {
                uint32_t ad = stg + (warp_m * 32 + mt * 16 + lm) * ROWB + kb;
                LDSM4(a_h[mt], ad + OFF_AH);
                LDSM4(a_l[mt], ad + OFF_AL);
            }
#pragma unroll
            for (int n2 = 0; n2 < 4; n2++) {
                uint32_t b_h[4], b_l[4];
                uint32_t bd = stg + (warp_n * 64 + n2 * 16 + lm) * ROWB + kb;
                LDSM4(b_h, bd + OFF_BH);
                LDSM4(b_l, bd + OFF_BL);
#pragma unroll
                for (int mt = 0; mt < 2; mt++)
#pragma unroll
                    for (int o = 0; o < 2; o++) {
                        const int nt = n2 * 2 + o;
                        MMA_BF16(acc[mt][nt], a_h[mt], b_h[o], b_h[o + 2]);
                        MMA_BF16(acc[mt][nt], a_h[mt], b_l[o], b_l[o + 2]);
                        MMA_BF16(acc[mt][nt], a_l[mt], b_h[o], b_h[o + 2]);
                    }
            }
        }
    }

    // ---- epilogue: registers -> gmem ----
    const float* biasz = bias + (size_t)z * N;
#pragma unroll
    for (int mt = 0; mt < 2; mt++) {
#pragma unroll
        for (int half = 0; half < 2; half++) {
            const int rtile = warp_m * 32 + mt * 16 + (lane >> 2) + half * 8;
            if (m0 + rtile >= cnt) continue;
            const size_t gr = (size_t)z * capRows + m0 + rtile;
#pragma unroll
            for (int nt = 0; nt < 8; nt++) {
                const int col = n0 + warp_n * 64 + nt * 8 + (lane & 3) * 2;
                float v0 = acc[mt][nt][half * 2 + 0] + biasz[col];
                float v1 = acc[mt][nt][half * 2 + 1] + biasz[col + 1];
                if (MODE == 1) { v0 = silu_f(v0); v1 = silu_f(v1); }
                if (MODE == 2) {
                    const float2 e = *(const float2*)&extra[gr * N + col];
                    v0 *= e.x; v1 *= e.y;
                }
                if (MODE == 3) {
                    const float2 e = *(const float2*)&extra[gr * N + col];
                    v0 += e.x; v1 += e.y;
                }
                if (C32) { float2 w = {v0, v1}; *(float2*)&C32[gr * N + col] = w; }
                if (Chi) {
                    __nv_bfloat16 h0 = __float2bfloat16(v0);
                    __nv_bfloat16 h1 = __float2bfloat16(v1);
                    __nv_bfloat162 hp; hp.x = h0; hp.y = h1;
                    *(__nv_bfloat162*)&Chi[gr * N + col] = hp;
                    __nv_bfloat162 lp;
                    lp.x = __float2bfloat16(v0 - __bfloat162float(h0));
                    lp.y = __float2bfloat16(v1 - __bfloat162float(h1));
                    *(__nv_bfloat162*)&Clo[gr * N + col] = lp;
                }
            }
        }
    }
}

// ---------------- small kernels ----------------
__global__ void conv_split_k(const float* __restrict__ in, __nv_bfloat16* __restrict__ hi,
                             __nv_bfloat16* __restrict__ lo, size_t n)
{
    size_t i = (size_t)blockIdx.x * blockDim.x + threadIdx.x;
    if (i >= n) return;
    float v = in[i];
    __nv_bfloat16 h = __float2bfloat16(v);
    hi[i] = h;
    lo[i] = __float2bfloat16(v - __bfloat162float(h));
}

// W [z, K, N] row-major -> out [(z*N + n), k]  (transpose + split)
__global__ void convT_k(const float* __restrict__ W, __nv_bfloat16* __restrict__ hi,
                        __nv_bfloat16* __restrict__ lo, int K, int N)
{
    __shared__ float t[32][33];
    const int n0 = blockIdx.x * 32, k0 = blockIdx.y * 32;
    const float* Wz = W + (size_t)blockIdx.z * K * N;
    for (int i = threadIdx.y; i < 32; i += 8)
        t[i][threadIdx.x] = Wz[(size_t)(k0 + i) * N + n0 + threadIdx.x];
    __syncthreads();
    for (int i = threadIdx.y; i < 32; i += 8) {
        size_t o = ((size_t)blockIdx.z * N + n0 + i) * K + k0 + threadIdx.x;
        float v = t[threadIdx.x][i];
        __nv_bfloat16 h = __float2bfloat16(v);
        hi[o] = h;
        lo[o] = __float2bfloat16(v - __bfloat162float(h));
    }
}

__global__ void zero_counts_k(int* counts) { if (threadIdx.x < EE) counts[threadIdx.x] = 0; }

__global__ void router_k(const float* __restrict__ p, const float* __restrict__ Wg,
                         int* __restrict__ counts, int* __restrict__ slot_token,
                         int* __restrict__ pair_slot, float* __restrict__ pair_gate)
{
    const int t = blockIdx.x;
    const int tid = threadIdx.x; // 128
    __shared__ float red[EE][128];
    float acc[EE];
#pragma unroll
    for (int e = 0; e < EE; e++) acc[e] = 0.f;
    const float* pr = p + (size_t)t * PP;
    for (int j = tid; j < PP; j += 128) {
        float pv = pr[j];
        const float* wg = Wg + (size_t)j * EE;
#pragma unroll
        for (int e = 0; e < EE; e++) acc[e] += pv * wg[e];
    }
#pragma unroll
    for (int e = 0; e < EE; e++) red[e][tid] = acc[e];
    __syncthreads();
    if (tid == 0) {
        float logit[EE];
        for (int e = 0; e < EE; e++) {
            float s = 0.f;
            for (int i = 0; i < 128; i++) s += red[e][i];
            logit[e] = s;
        }
        int i0 = 0;
        for (int e = 1; e < EE; e++) if (logit[e] > logit[i0]) i0 = e;
        int i1 = (i0 == 0) ? 1 : 0;
        for (int e = 0; e < EE; e++) {
            if (e == i0) continue;
            if (logit[e] > logit[i1]) i1 = e;
        }
        float g0 = 1.f / (1.f + expf(logit[i1] - logit[i0]));
        float g1 = 1.f - g0;
        int s0 = atomicAdd(&counts[i0], 1);
        int s1 = atomicAdd(&counts[i1], 1);
        slot_token[i0 * CAP + s0] = t;
        slot_token[i1 * CAP + s1] = t;
        pair_slot[2 * t]     = i0 * CAP + s0;
        pair_slot[2 * t + 1] = i1 * CAP + s1;
        pair_gate[2 * t]     = g0;
        pair_gate[2 * t + 1] = g1;
    }
}

__global__ void combine_k(const float* __restrict__ eo, const int* __restrict__ pair_slot,
                          const float* __restrict__ pair_gate, float* __restrict__ moe)
{
    int idx = blockIdx.x * blockDim.x + threadIdx.x;
    if (idx >= B_TOK * PP) return;
    int t = idx >> 10, j = idx & (PP - 1);
    int s0 = pair_slot[2 * t], s1 = pair_slot[2 * t + 1];
    float g0 = pair_gate[2 * t], g1 = pair_gate[2 * t + 1];
    moe[idx] = g0 * eo[(size_t)s0 * PP + j] + g1 * eo[(size_t)s1 * PP + j];
}

// ---------------- head: tiled, 32 tokens per block, 29 outputs ----------------
#define HKC 128
__global__ __launch_bounds__(928)
void head2_k(const float* __restrict__ hid2, const float* __restrict__ head_w,
             const float* __restrict__ head_b, float* __restrict__ out)
{
    __shared__ float hs[32 * HKC];       // 16 KB
    __shared__ float ws[HKC * 30];       // 15 KB (stride 30 to dodge conflicts)
    const int tid = threadIdx.x;         // 928 = 32 tok * 29 out
    const int tok0 = blockIdx.x * 32;
    const int tokl = tid / OUTN;
    const int o    = tid % OUTN;
    float acc = 0.f;

    for (int kc = 0; kc < HH; kc += HKC) {
        for (int i = tid; i < 32 * HKC; i += 928)
            hs[i] = hid2[(size_t)(tok0 + (i >> 7)) * HH + kc + (i & (HKC - 1))];
        for (int i = tid; i < HKC * OUTN; i += 928) {
            int k = i / OUTN, oo = i % OUTN;
            ws[k * 30 + oo] = head_w[(size_t)(kc + k) * OUTN + oo];
        }
        __syncthreads();
        const float* hrow = hs + tokl * HKC;
#pragma unroll 4
        for (int k = 0; k < HKC; k++)
            acc += hrow[k] * ws[k * 30 + o];
        __syncthreads();
    }
    out[(size_t)(tok0 + tokl) * OUTN + o] = acc + head_b[o];
}

// ---------------- launch ----------------
template <typename T>
static T* symaddr(const void* sym) { void* p = nullptr; cudaGetSymbolAddress(&p, sym); return (T*)p; }

extern "C" void kernel_launch(void* const* d_in, const int* in_sizes, int n_in,
                              void* d_out, int out_size)
{
    const float* x      = (const float*)d_in[0];
    const float* Wproj  = (const float*)d_in[1];
    const float* bproj  = (const float*)d_in[2];
    const float* Wg     = (const float*)d_in[3];
    const float* W1     = (const float*)d_in[4];
    const float* b1     = (const float*)d_in[5];
    const float* W2     = (const float*)d_in[6];
    const float* b2     = (const float*)d_in[7];
    const float* sg_w   = (const float*)d_in[8];
    const float* sg_b   = (const float*)d_in[9];
    const float* su_w   = (const float*)d_in[10];
    const float* su_b   = (const float*)d_in[11];
    const float* sd_w   = (const float*)d_in[12];
    const float* sd_b   = (const float*)d_in[13];
    const float* m1_w   = (const float*)d_in[14];
    const float* m1_b   = (const float*)d_in[15];
    const float* m2_w   = (const float*)d_in[16];
    const float* m2_b   = (const float*)d_in[17];
    const float* head_w = (const float*)d_in[18];
    const float* head_b = (const float*)d_in[19];
    float* out = (float*)d_out;

    static bool attr_done = false;
    if (!attr_done) {
        cudaFuncSetAttribute(mm_gemm<0, false>, cudaFuncAttributeMaxDynamicSharedMemorySize, SMEM_BYTES);
        cudaFuncSetAttribute(mm_gemm<1, false>, cudaFuncAttributeMaxDynamicSharedMemorySize, SMEM_BYTES);
        cudaFuncSetAttribute(mm_gemm<2, false>, cudaFuncAttributeMaxDynamicSharedMemorySize, SMEM_BYTES);
        cudaFuncSetAttribute(mm_gemm<3, false>, cudaFuncAttributeMaxDynamicSharedMemorySize, SMEM_BYTES);
        cudaFuncSetAttribute(mm_gemm<0, true>,  cudaFuncAttributeMaxDynamicSharedMemorySize, SMEM_BYTES);
        cudaFuncSetAttribute(mm_gemm<1, true>,  cudaFuncAttributeMaxDynamicSharedMemorySize, SMEM_BYTES);
        attr_done = true;
    }

    __nv_bfloat16 *x_hi = symaddr<__nv_bfloat16>(g_x_hi),  *x_lo = symaddr<__nv_bfloat16>(g_x_lo);
    __nv_bfloat16 *p_hi = symaddr<__nv_bfloat16>(g_p_hi),  *p_lo = symaddr<__nv_bfloat16>(g_p_lo);
    float *p32  = symaddr<float>(g_p32);
    __nv_bfloat16 *h_hi  = symaddr<__nv_bfloat16>(g_h_hi),  *h_lo  = symaddr<__nv_bfloat16>(g_h_lo);
    float *eo32 = symaddr<float>(g_eo32);
    float *moe  = symaddr<float>(g_moe);
    float *sg32 = symaddr<float>(g_sg32);
    __nv_bfloat16 *su_hi = symaddr<__nv_bfloat16>(g_su_hi), *su_lo = symaddr<__nv_bfloat16>(g_su_lo);
    __nv_bfloat16 *cb_hi = symaddr<__nv_bfloat16>(g_cb_hi), *cb_lo = symaddr<__nv_bfloat16>(g_cb_lo);
    __nv_bfloat16 *h1_hi = symaddr<__nv_bfloat16>(g_h1_hi), *h1_lo = symaddr<__nv_bfloat16>(g_h1_lo);
    float *h232 = symaddr<float>(g_h232);
    __nv_bfloat16 *wp_hi = symaddr<__nv_bfloat16>(g_wp_hi), *wp_lo = symaddr<__nv_bfloat16>(g_wp_lo);
    __nv_bfloat16 *w1_hi = symaddr<__nv_bfloat16>(g_w1_hi), *w1_lo = symaddr<__nv_bfloat16>(g_w1_lo);
    __nv_bfloat16 *w2_hi = symaddr<__nv_bfloat16>(g_w2_hi), *w2_lo = symaddr<__nv_bfloat16>(g_w2_lo);
    __nv_bfloat16 *sgw_hi = symaddr<__nv_bfloat16>(g_sgw_hi), *sgw_lo = symaddr<__nv_bfloat16>(g_sgw_lo);
    __nv_bfloat16 *suw_hi = symaddr<__nv_bfloat16>(g_suw_hi), *suw_lo = symaddr<__nv_bfloat16>(g_suw_lo);
    __nv_bfloat16 *sdw_hi = symaddr<__nv_bfloat16>(g_sdw_hi), *sdw_lo = symaddr<__nv_bfloat16>(g_sdw_lo);
    __nv_bfloat16 *m1_hi = symaddr<__nv_bfloat16>(g_m1_hi), *m1_lo = symaddr<__nv_bfloat16>(g_m1_lo);
    __nv_bfloat16 *m2_hi = symaddr<__nv_bfloat16>(g_m2_hi), *m2_lo = symaddr<__nv_bfloat16>(g_m2_lo);
    int *counts = symaddr<int>(g_counts);
    int *stok   = symaddr<int>(g_slot_token);
    int *pslot  = symaddr<int>(g_pair_slot);
    float *pgate = symaddr<float>(g_pair_gate);

    // ---- split inputs / transpose+split weights ----
    conv_split_k<<<(B_TOK * DIN + 255) / 256, 256>>>(x, x_hi, x_lo, (size_t)B_TOK * DIN);
    convT_k<<<dim3(PP / 32, DIN / 32, 1),  dim3(32, 8)>>>(Wproj, wp_hi, wp_lo, DIN, PP);
    convT_k<<<dim3(HH / 32, PP / 32, EE),  dim3(32, 8)>>>(W1, w1_hi, w1_lo, PP, HH);
    convT_k<<<dim3(PP / 32, HH / 32, EE),  dim3(32, 8)>>>(W2, w2_hi, w2_lo, HH, PP);
    convT_k<<<dim3(HSH / 32, PP / 32, 1),  dim3(32, 8)>>>(sg_w, sgw_hi, sgw_lo, PP, HSH);
    convT_k<<<dim3(HSH / 32, PP / 32, 1),  dim3(32, 8)>>>(su_w, suw_hi, suw_lo, PP, HSH);
    convT_k<<<dim3(PP / 32, HSH / 32, 1),  dim3(32, 8)>>>(sd_w, sdw_hi, sdw_lo, HSH, PP);
    convT_k<<<dim3(HH / 32, PP / 32, 1),   dim3(32, 8)>>>(m1_w, m1_hi, m1_lo, PP, HH);
    convT_k<<<dim3(HH / 32, HH / 32, 1),   dim3(32, 8)>>>(m2_w, m2_hi, m2_lo, HH, HH);

    // 1. p = x @ Wproj + bproj
    mm_gemm<0, false><<<dim3(PP / BN, B_TOK / BM, 1), NTHR, SMEM_BYTES>>>(
        x_hi, x_lo, wp_hi, wp_lo, bproj, nullptr, p32, p_hi, p_lo,
        nullptr, nullptr, B_TOK, PP, DIN);
    // 2. router
    zero_counts_k<<<1, 32>>>(counts);
    router_k<<<B_TOK, 128>>>(p32, Wg, counts, stok, pslot, pgate);
    // 3. expert fc1 (A gathered via slot_token -- pack fused)
    mm_gemm<1, true><<<dim3(HH / BN, CAP / BM, EE), NTHR, SMEM_BYTES>>>(
        p_hi, p_lo, w1_hi, w1_lo, b1, nullptr, nullptr, h_hi, h_lo,
        counts, stok, CAP, HH, PP);
    // 4. expert fc2
    mm_gemm<0, false><<<dim3(PP / BN, CAP / BM, EE), NTHR, SMEM_BYTES>>>(
        h_hi, h_lo, w2_hi, w2_lo, b2, nullptr, eo32, nullptr, nullptr,
        counts, nullptr, CAP, PP, HH);
    // 5. combine
    combine_k<<<(B_TOK * PP + 255) / 256, 256>>>(eo32, pslot, pgate, moe);
    // 6. shared SwiGLU
    mm_gemm<1, false><<<dim3(HSH / BN, B_TOK / BM, 1), NTHR, SMEM_BYTES>>>(
        p_hi, p_lo, sgw_hi, sgw_lo, sg_b, nullptr, sg32, nullptr, nullptr,
        nullptr, nullptr, B_TOK, HSH, PP);
    mm_gemm<2, false><<<dim3(HSH / BN, B_TOK / BM, 1), NTHR, SMEM_BYTES>>>(
        p_hi, p_lo, suw_hi, suw_lo, su_b, sg32, nullptr, su_hi, su_lo,
        nullptr, nullptr, B_TOK, HSH, PP);
    // 7. down proj + moe residual
    mm_gemm<3, false><<<dim3(PP / BN, B_TOK / BM, 1), NTHR, SMEM_BYTES>>>(
        su_hi, su_lo, sdw_hi, sdw_lo, sd_b, moe, nullptr, cb_hi, cb_lo,
        nullptr, nullptr, B_TOK, PP, HSH);
    // 8. output MLP
    mm_gemm<1, false><<<dim3(HH / BN, B_TOK / BM, 1), NTHR, SMEM_BYTES>>>(
        cb_hi, cb_lo, m1_hi, m1_lo, m1_b, nullptr, nullptr, h1_hi, h1_lo,
        nullptr, nullptr, B_TOK, HH, PP);
    mm_gemm<0, false><<<dim3(HH / BN, B_TOK / BM, 1), NTHR, SMEM_BYTES>>>(
        h1_hi, h1_lo, m2_hi, m2_lo, m2_b, nullptr, h232, nullptr, nullptr,
        nullptr, nullptr, B_TOK, HH, HH);
    // 9. head (tiled)
    head2_k<<<B_TOK / 32, 928>>>(h232, head_w, head_b, out);
}

// round 11
// speedup vs baseline: 2.9823x; 1.0354x over previous
#include <cuda_runtime.h>
#include <cuda_bf16.h>
#include <math.h>
#include <stdint.h>

// ---------------- problem constants ----------------
#define B_TOK 4096
#define DIN   512
#define PP    1024
#define HH    2048
#define EE    8
#define HSH   4096
#define OUTN  29
#define CAP   4096

// ---------------- mma.sync GEMM tile config (proven r8/r10) ----------------
#define BM 128
#define BN 256
#define BKC 32
#define ROWB 80
#define OFF_AH 0
#define OFF_AL (128 * ROWB)
#define OFF_BH (256 * ROWB)
#define OFF_BL (256 * ROWB + 256 * ROWB)
#define STAGE_BYTES (768 * ROWB)
#define NSTAGE 3
#define SMEM_BYTES (NSTAGE * STAGE_BYTES)
#define NTHR 512

// ---------------- PTX helpers ----------------
__device__ __forceinline__ uint32_t smem_u32(const void* p) {
    uint32_t a;
    asm("{ .reg .u64 t; cvta.to.shared.u64 t, %1; cvt.u32.u64 %0, t; }" : "=r"(a) : "l"(p));
    return a;
}
#define CP16(dst, src) asm volatile("cp.async.cg.shared.global [%0], [%1], 16;" :: "r"(dst), "l"(src) : "memory")
#define CP_COMMIT()    asm volatile("cp.async.commit_group;" ::: "memory")

#define LDSM4(r, addr) \
    asm volatile("ldmatrix.sync.aligned.m8n8.x4.shared.b16 {%0,%1,%2,%3}, [%4];" \
        : "=r"((r)[0]), "=r"((r)[1]), "=r"((r)[2]), "=r"((r)[3]) : "r"(addr))

#define MMA_BF16(c, a, b0, b1) \
    asm volatile("mma.sync.aligned.m16n8k16.row.col.f32.bf16.bf16.f32 " \
        "{%0,%1,%2,%3}, {%4,%5,%6,%7}, {%8,%9}, {%0,%1,%2,%3};" \
        : "+f"((c)[0]), "+f"((c)[1]), "+f"((c)[2]), "+f"((c)[3]) \
        : "r"((a)[0]), "r"((a)[1]), "r"((a)[2]), "r"((a)[3]), "r"(b0), "r"(b1))

// ---------------- scratch (device globals) ----------------
#define DEV __device__ __align__(128)
DEV __nv_bfloat16 g_x_hi [B_TOK * DIN],   g_x_lo [B_TOK * DIN];
DEV __nv_bfloat16 g_p_hi [B_TOK * PP],    g_p_lo [B_TOK * PP];
DEV float         g_p32  [B_TOK * PP];
DEV __nv_bfloat16 g_h_hi [(size_t)EE * CAP * HH], g_h_lo [(size_t)EE * CAP * HH];
DEV float         g_eo32 [(size_t)EE * CAP * PP];
DEV float         g_moe  [B_TOK * PP];
DEV __nv_bfloat16 g_su_hi[(size_t)B_TOK * HSH],   g_su_lo[(size_t)B_TOK * HSH];
DEV __nv_bfloat16 g_cb_hi[B_TOK * PP],    g_cb_lo[B_TOK * PP];
DEV __nv_bfloat16 g_h1_hi[B_TOK * HH],    g_h1_lo[B_TOK * HH];
DEV float         g_h232 [B_TOK * HH];
DEV __nv_bfloat16 g_wp_hi [PP * DIN],     g_wp_lo [PP * DIN];
DEV __nv_bfloat16 g_w1_hi [EE * HH * PP], g_w1_lo [EE * HH * PP];
DEV __nv_bfloat16 g_w2_hi [EE * PP * HH], g_w2_lo [EE * PP * HH];
DEV __nv_bfloat16 g_guw_hi[(size_t)2 * HSH * PP], g_guw_lo[(size_t)2 * HSH * PP]; // interleaved gate/up
DEV float         g_gub   [2 * HSH];
DEV __nv_bfloat16 g_sdw_hi[PP * HSH],     g_sdw_lo[PP * HSH];
DEV __nv_bfloat16 g_m1_hi [HH * PP],      g_m1_lo [HH * PP];
DEV __nv_bfloat16 g_m2_hi [HH * HH],      g_m2_lo [HH * HH];
DEV int   g_counts[EE];
DEV int   g_slot_token[EE * CAP];
DEV int   g_pair_slot[B_TOK * 2];
DEV float g_pair_gate[B_TOK * 2];

__device__ __forceinline__ float silu_f(float x) { return x / (1.0f + expf(-x)); }

// ---------------- stage fill (512 threads): A 128 rows + B 256 rows, hi+lo ----------------
template<bool GATHER>
__device__ __forceinline__ void fill_stage(uint32_t st, int tid,
    const char* Ah, const char* Al, const char* Bh, const char* Bl,
    size_t Kb, long rowA0, long rowB0, const int* __restrict__ tokRow, size_t kByte)
{
    {
        int row = tid >> 2, ch = tid & 3;
        uint32_t d = st + row * ROWB + ch * 16;
        long arow = GATHER ? (long)tokRow[row] : (rowA0 + row);
        size_t s = (size_t)arow * Kb + kByte + ch * 16;
        CP16(d + OFF_AH, Ah + s);
        CP16(d + OFF_AL, Al + s);
    }
#pragma unroll
    for (int i = 0; i < 2; i++) {
        int p = tid + (i << 9);
        int row = p >> 2, ch = p & 3;
        uint32_t d = st + row * ROWB + ch * 16;
        size_t s = (size_t)(rowB0 + row) * Kb + kByte + ch * 16;
        CP16(d + OFF_BH, Bh + s);
        CP16(d + OFF_BL, Bl + s);
    }
    CP_COMMIT();
}

// ---------------- bf16-split x3 GEMM, 16 warps, warp tile 32x64 ----------------
// MODE: 0=+bias 1=silu(+bias) 3=(+bias)+extra 4=fused SwiGLU pairs (even=gate, odd=up)
template<int MODE, bool GATHER>
__global__ __launch_bounds__(NTHR, 1)
void mm_gemm(const __nv_bfloat16* __restrict__ Ahi, const __nv_bfloat16* __restrict__ Alo,
             const __nv_bfloat16* __restrict__ Bhi, const __nv_bfloat16* __restrict__ Blo,
             const float* __restrict__ bias, const float* __restrict__ extra,
             float* __restrict__ C32, __nv_bfloat16* __restrict__ Chi,
             __nv_bfloat16* __restrict__ Clo,
             const int* __restrict__ counts, const int* __restrict__ stok,
             int capRows, int N, int K)
{
    const int z  = blockIdx.z;
    const int m0 = blockIdx.y * BM;
    const int n0 = blockIdx.x * BN;
    int cnt = capRows;
    if (counts) { cnt = counts[z]; if (m0 >= cnt) return; }

    extern __shared__ __align__(128) char smem[];
    const uint32_t sb = smem_u32(smem);
    const int tid = threadIdx.x, lane = tid & 31, wid = tid >> 5;
    const int warp_m = wid & 3;
    const int warp_n = wid >> 2;

    const size_t Kb = (size_t)K * 2;
    const long rowA0 = (long)z * capRows + m0;
    const long rowB0 = (long)z * N + n0;
    const int* tokRow = GATHER ? (stok + z * CAP + m0) : nullptr;
    const int  C = K / BKC;

    float acc[2][8][4];
#pragma unroll
    for (int i = 0; i < 2; i++)
#pragma unroll
        for (int j = 0; j < 8; j++)
#pragma unroll
            for (int q = 0; q < 4; q++) acc[i][j][q] = 0.f;

    const char* Ah = (const char*)Ahi; const char* Al = (const char*)Alo;
    const char* Bh = (const char*)Bhi; const char* Bl = (const char*)Blo;

    fill_stage<GATHER>(sb, tid, Ah, Al, Bh, Bl, Kb, rowA0, rowB0, tokRow, 0);
    if (C > 1) fill_stage<GATHER>(sb + STAGE_BYTES, tid, Ah, Al, Bh, Bl, Kb, rowA0, rowB0, tokRow, 64);

    const int lm = lane & 15;
    const int lkb = (lane >> 4) << 4;

    for (int c = 0; c < C; c++) {
        if (c + 2 < C) asm volatile("cp.async.wait_group 1;" ::: "memory");
        else           asm volatile("cp.async.wait_group 0;" ::: "memory");
        __syncthreads();
        if (c + 2 < C)
            fill_stage<GATHER>(sb + ((c + 2) % NSTAGE) * STAGE_BYTES, tid, Ah, Al, Bh, Bl,
                               Kb, rowA0, rowB0, tokRow, (size_t)(c + 2) * 64);

        const uint32_t stg = sb + (c % NSTAGE) * STAGE_BYTES;
#pragma unroll
        for (int kk = 0; kk < 2; kk++) {
            const uint32_t kb = kk * 32 + lkb;
            uint32_t a_h[2][4], a_l[2][4];
#pragma unroll
            for (int mt = 0; mt < 2; mt++) {
                uint32_t ad = stg + (warp_m * 32 + mt * 16 + lm) * ROWB + kb;
                LDSM4(a_h[mt], ad + OFF_AH);
                LDSM4(a_l[mt], ad + OFF_AL);
            }
#pragma unroll
            for (int n2 = 0; n2 < 4; n2++) {
                uint32_t b_h[4], b_l[4];
                uint32_t bd = stg + (warp_n * 64 + n2 * 16 + lm) * ROWB + kb;
                LDSM4(b_h, bd + OFF_BH);
                LDSM4(b_l, bd + OFF_BL);
#pragma unroll
                for (int mt = 0; mt < 2; mt++)
#pragma unroll
                    for (int o = 0; o < 2; o++) {
                        const int nt = n2 * 2 + o;
                        MMA_BF16(acc[mt][nt], a_h[mt], b_h[o], b_h[o + 2]);
                        MMA_BF16(acc[mt][nt], a_h[mt], b_l[o], b_l[o + 2]);
                        MMA_BF16(acc[mt][nt], a_l[mt], b_h[o], b_h[o + 2]);
                    }
            }
        }
    }

    // ---- epilogue ----
    const float* biasz = bias + (size_t)z * N;
#pragma unroll
    for (int mt = 0; mt < 2; mt++) {
#pragma unroll
        for (int half = 0; half < 2; half++) {
            const int rtile = warp_m * 32 + mt * 16 + (lane >> 2) + half * 8;
            if (m0 + rtile >= cnt) continue;
            const size_t gr = (size_t)z * capRows + m0 + rtile;
#pragma unroll
            for (int nt = 0; nt < 8; nt++) {
                const int col = n0 + warp_n * 64 + nt * 8 + (lane & 3) * 2;
                float v0 = acc[mt][nt][half * 2 + 0] + biasz[col];
                float v1 = acc[mt][nt][half * 2 + 1] + biasz[col + 1];
                if (MODE == 4) {
                    // fused SwiGLU: v0 = gate, v1 = up (interleaved weights)
                    float w = silu_f(v0) * v1;
                    __nv_bfloat16 h = __float2bfloat16(w);
                    const size_t o = gr * (size_t)(N >> 1) + (col >> 1);
                    Chi[o] = h;
                    Clo[o] = __float2bfloat16(w - __bfloat162float(h));
                    continue;
                }
                if (MODE == 1) { v0 = silu_f(v0); v1 = silu_f(v1); }
                if (MODE == 3) {
                    const float2 e = *(const float2*)&extra[gr * N + col];
                    v0 += e.x; v1 += e.y;
                }
                if (C32) { float2 w = {v0, v1}; *(float2*)&C32[gr * N + col] = w; }
                if (Chi) {
                    __nv_bfloat16 h0 = __float2bfloat16(v0);
                    __nv_bfloat16 h1 = __float2bfloat16(v1);
                    __nv_bfloat162 hp; hp.x = h0; hp.y = h1;
                    *(__nv_bfloat162*)&Chi[gr * N + col] = hp;
                    __nv_bfloat162 lp;
                    lp.x = __float2bfloat16(v0 - __bfloat162float(h0));
                    lp.y = __float2bfloat16(v1 - __bfloat162float(h1));
                    *(__nv_bfloat162*)&Clo[gr * N + col] = lp;
                }
            }
        }
    }
}

// ---------------- small kernels ----------------
__global__ void conv_split_k(const float* __restrict__ in, __nv_bfloat16* __restrict__ hi,
                             __nv_bfloat16* __restrict__ lo, size_t n)
{
    size_t i = (size_t)blockIdx.x * blockDim.x + threadIdx.x;
    if (i >= n) return;
    float v = in[i];
    __nv_bfloat16 h = __float2bfloat16(v);
    hi[i] = h;
    lo[i] = __float2bfloat16(v - __bfloat162float(h));
}

// vectorized transpose + split: W [z, K, N] -> out [(z*N + n)*RMUL + radd, k]
// tile 32(K) x 128(N); coalesced reads; bf16x2 stores; conflict-free smem
template<int RMUL>
__global__ __launch_bounds__(256)
void convT2_k(const float* __restrict__ W, __nv_bfloat16* __restrict__ hi,
              __nv_bfloat16* __restrict__ lo, int K, int N, int radd)
{
    __shared__ float t[32][129];
    const int k0 = blockIdx.y * 32, n0 = blockIdx.x * 128;
    const float* Wz = W + (size_t)blockIdx.z * K * N;
    const int tid = threadIdx.x;
    {
        const int c = tid & 127;
        for (int r = tid >> 7; r < 32; r += 2)
            t[r][c] = Wz[(size_t)(k0 + r) * N + n0 + c];
    }
    __syncthreads();
    const size_t zbase = (size_t)blockIdx.z * N * RMUL;
    for (int idx = tid; idx < 128 * 16; idx += 256) {
        const int n = idx >> 4, kp = idx & 15;
        float v0 = t[kp * 2][n], v1 = t[kp * 2 + 1][n];
        __nv_bfloat16 h0 = __float2bfloat16(v0), h1 = __float2bfloat16(v1);
        __nv_bfloat162 hp; hp.x = h0; hp.y = h1;
        __nv_bfloat162 lp;
        lp.x = __float2bfloat16(v0 - __bfloat162float(h0));
        lp.y = __float2bfloat16(v1 - __bfloat162float(h1));
        const size_t orow = zbase + (size_t)(n0 + n) * RMUL + radd;
        const size_t o = orow * K + k0 + kp * 2;
        *(__nv_bfloat162*)&hi[o] = hp;
        *(__nv_bfloat162*)&lo[o] = lp;
    }
}

__global__ void ileave_bias_k(const float* __restrict__ a, const float* __restrict__ b,
                              float* __restrict__ o, int n)
{
    int i = blockIdx.x * 256 + threadIdx.x;
    if (i < n) { o[2 * i] = a[i]; o[2 * i + 1] = b[i]; }
}

__global__ void zero_counts_k(int* counts) { if (threadIdx.x < EE) counts[threadIdx.x] = 0; }

__global__ void router_k(const float* __restrict__ p, const float* __restrict__ Wg,
                         int* __restrict__ counts, int* __restrict__ slot_token,
                         int* __restrict__ pair_slot, float* __restrict__ pair_gate)
{
    const int t = blockIdx.x;
    const int tid = threadIdx.x; // 128
    __shared__ float red[EE][128];
    float acc[EE];
#pragma unroll
    for (int e = 0; e < EE; e++) acc[e] = 0.f;
    const float* pr = p + (size_t)t * PP;
    for (int j = tid; j < PP; j += 128) {
        float pv = pr[j];
        const float* wg = Wg + (size_t)j * EE;
#pragma unroll
        for (int e = 0; e < EE; e++) acc[e] += pv * wg[e];
    }
#pragma unroll
    for (int e = 0; e < EE; e++) red[e][tid] = acc[e];
    __syncthreads();
    if (tid == 0) {
        float logit[EE];
        for (int e = 0; e < EE; e++) {
            float s = 0.f;
            for (int i = 0; i < 128; i++) s += red[e][i];
            logit[e] = s;
        }
        int i0 = 0;
        for (int e = 1; e < EE; e++) if (logit[e] > logit[i0]) i0 = e;
        int i1 = (i0 == 0) ? 1 : 0;
        for (int e = 0; e < EE; e++) {
            if (e == i0) continue;
            if (logit[e] > logit[i1]) i1 = e;
        }
        float g0 = 1.f / (1.f + expf(logit[i1] - logit[i0]));
        float g1 = 1.f - g0;
        int s0 = atomicAdd(&counts[i0], 1);
        int s1 = atomicAdd(&counts[i1], 1);
        slot_token[i0 * CAP + s0] = t;
        slot_token[i1 * CAP + s1] = t;
        pair_slot[2 * t]     = i0 * CAP + s0;
        pair_slot[2 * t + 1] = i1 * CAP + s1;
        pair_gate[2 * t]     = g0;
        pair_gate[2 * t + 1] = g1;
    }
}

__global__ void combine_k(const float* __restrict__ eo, const int* __restrict__ pair_slot,
                          const float* __restrict__ pair_gate, float* __restrict__ moe)
{
    int idx = blockIdx.x * blockDim.x + threadIdx.x;
    if (idx >= B_TOK * PP) return;
    int t = idx >> 10, j = idx & (PP - 1);
    int s0 = pair_slot[2 * t], s1 = pair_slot[2 * t + 1];
    float g0 = pair_gate[2 * t], g1 = pair_gate[2 * t + 1];
    moe[idx] = g0 * eo[(size_t)s0 * PP + j] + g1 * eo[(size_t)s1 * PP + j];
}

// ---------------- head: tiled, 32 tokens per block ----------------
#define HKC 128
__global__ __launch_bounds__(928)
void head2_k(const float* __restrict__ hid2, const float* __restrict__ head_w,
             const float* __restrict__ head_b, float* __restrict__ out)
{
    __shared__ float hs[32 * HKC];
    __shared__ float ws[HKC * 30];
    const int tid = threadIdx.x;        // 928 = 32 tok * 29 out
    const int tok0 = blockIdx.x * 32;
    const int tokl = tid / OUTN;
    const int o    = tid % OUTN;
    float acc = 0.f;

    for (int kc = 0; kc < HH; kc += HKC) {
        for (int i = tid; i < 32 * HKC; i += 928)
            hs[i] = hid2[(size_t)(tok0 + (i >> 7)) * HH + kc + (i & (HKC - 1))];
        for (int i = tid; i < HKC * OUTN; i += 928) {
            int k = i / OUTN, oo = i % OUTN;
            ws[k * 30 + oo] = head_w[(size_t)(kc + k) * OUTN + oo];
        }
        __syncthreads();
        const float* hrow = hs + tokl * HKC;
#pragma unroll 4
        for (int k = 0; k < HKC; k++)
            acc += hrow[k] * ws[k * 30 + o];
        __syncthreads();
    }
    out[(size_t)(tok0 + tokl) * OUTN + o] = acc + head_b[o];
}

// ---------------- launch ----------------
template <typename T>
static T* symaddr(const void* sym) { void* p = nullptr; cudaGetSymbolAddress(&p, sym); return (T*)p; }

extern "C" void kernel_launch(void* const* d_in, const int* in_sizes, int n_in,
                              void* d_out, int out_size)
{
    const float* x      = (const float*)d_in[0];
    const float* Wproj  = (const float*)d_in[1];
    const float* bproj  = (const float*)d_in[2];
    const float* Wg     = (const float*)d_in[3];
    const float* W1     = (const float*)d_in[4];
    const float* b1     = (const float*)d_in[5];
    const float* W2     = (const float*)d_in[6];
    const float* b2     = (const float*)d_in[7];
    const float* sg_w   = (const float*)d_in[8];
    const float* sg_b   = (const float*)d_in[9];
    const float* su_w   = (const float*)d_in[10];
    const float* su_b   = (const float*)d_in[11];
    const float* sd_w   = (const float*)d_in[12];
    const float* sd_b   = (const float*)d_in[13];
    const float* m1_w   = (const float*)d_in[14];
    const float* m1_b   = (const float*)d_in[15];
    const float* m2_w   = (const float*)d_in[16];
    const float* m2_b   = (const float*)d_in[17];
    const float* head_w = (const float*)d_in[18];
    const float* head_b = (const float*)d_in[19];
    float* out = (float*)d_out;

    static bool attr_done = false;
    if (!attr_done) {
        cudaFuncSetAttribute(mm_gemm<0, false>, cudaFuncAttributeMaxDynamicSharedMemorySize, SMEM_BYTES);
        cudaFuncSetAttribute(mm_gemm<1, false>, cudaFuncAttributeMaxDynamicSharedMemorySize, SMEM_BYTES);
        cudaFuncSetAttribute(mm_gemm<3, false>, cudaFuncAttributeMaxDynamicSharedMemorySize, SMEM_BYTES);
        cudaFuncSetAttribute(mm_gemm<4, false>, cudaFuncAttributeMaxDynamicSharedMemorySize, SMEM_BYTES);
        cudaFuncSetAttribute(mm_gemm<1, true>,  cudaFuncAttributeMaxDynamicSharedMemorySize, SMEM_BYTES);
        attr_done = true;
    }

    __nv_bfloat16 *x_hi = symaddr<__nv_bfloat16>(g_x_hi),  *x_lo = symaddr<__nv_bfloat16>(g_x_lo);
    __nv_bfloat16 *p_hi = symaddr<__nv_bfloat16>(g_p_hi),  *p_lo = symaddr<__nv_bfloat16>(g_p_lo);
    float *p32  = symaddr<float>(g_p32);
    __nv_bfloat16 *h_hi  = symaddr<__nv_bfloat16>(g_h_hi),  *h_lo  = symaddr<__nv_bfloat16>(g_h_lo);
    float *eo32 = symaddr<float>(g_eo32);
    float *moe  = symaddr<float>(g_moe);
    __nv_bfloat16 *su_hi = symaddr<__nv_bfloat16>(g_su_hi), *su_lo = symaddr<__nv_bfloat16>(g_su_lo);
    __nv_bfloat16 *cb_hi = symaddr<__nv_bfloat16>(g_cb_hi), *cb_lo = symaddr<__nv_bfloat16>(g_cb_lo);
    __nv_bfloat16 *h1_hi = symaddr<__nv_bfloat16>(g_h1_hi), *h1_lo = symaddr<__nv_bfloat16>(g_h1_lo);
    float *h232 = symaddr<float>(g_h232);
    __nv_bfloat16 *wp_hi = symaddr<__nv_bfloat16>(g_wp_hi), *wp_lo = symaddr<__nv_bfloat16>(g_wp_lo);
    __nv_bfloat16 *w1_hi = symaddr<__nv_bfloat16>(g_w1_hi), *w1_lo = symaddr<__nv_bfloat16>(g_w1_lo);
    __nv_bfloat16 *w2_hi = symaddr<__nv_bfloat16>(g_w2_hi), *w2_lo = symaddr<__nv_bfloat16>(g_w2_lo);
    __nv_bfloat16 *guw_hi = symaddr<__nv_bfloat16>(g_guw_hi), *guw_lo = symaddr<__nv_bfloat16>(g_guw_lo);
    float *gub = symaddr<float>(g_gub);
    __nv_bfloat16 *sdw_hi = symaddr<__nv_bfloat16>(g_sdw_hi), *sdw_lo = symaddr<__nv_bfloat16>(g_sdw_lo);
    __nv_bfloat16 *m1_hi = symaddr<__nv_bfloat16>(g_m1_hi), *m1_lo = symaddr<__nv_bfloat16>(g_m1_lo);
    __nv_bfloat16 *m2_hi = symaddr<__nv_bfloat16>(g_m2_hi), *m2_lo = symaddr<__nv_bfloat16>(g_m2_lo);
    int *counts = symaddr<int>(g_counts);
    int *stok   = symaddr<int>(g_slot_token);
    int *pslot  = symaddr<int>(g_pair_slot);
    float *pgate = symaddr<float>(g_pair_gate);

    // ---- split input / transpose+split weights (vectorized) ----
    conv_split_k<<<(B_TOK * DIN + 255) / 256, 256>>>(x, x_hi, x_lo, (size_t)B_TOK * DIN);
    convT2_k<1><<<dim3(PP / 128, DIN / 32, 1),  256>>>(Wproj, wp_hi, wp_lo, DIN, PP, 0);
    convT2_k<1><<<dim3(HH / 128, PP / 32, EE),  256>>>(W1, w1_hi, w1_lo, PP, HH, 0);
    convT2_k<1><<<dim3(PP / 128, HH / 32, EE),  256>>>(W2, w2_hi, w2_lo, HH, PP, 0);
    convT2_k<2><<<dim3(HSH / 128, PP / 32, 1),  256>>>(sg_w, guw_hi, guw_lo, PP, HSH, 0); // even rows
    convT2_k<2><<<dim3(HSH / 128, PP / 32, 1),  256>>>(su_w, guw_hi, guw_lo, PP, HSH, 1); // odd rows
    convT2_k<1><<<dim3(PP / 128, HSH / 32, 1),  256>>>(sd_w, sdw_hi, sdw_lo, HSH, PP, 0);
    convT2_k<1><<<dim3(HH / 128, PP / 32, 1),   256>>>(m1_w, m1_hi, m1_lo, PP, HH, 0);
    convT2_k<1><<<dim3(HH / 128, HH / 32, 1),   256>>>(m2_w, m2_hi, m2_lo, HH, HH, 0);
    ileave_bias_k<<<(HSH + 255) / 256, 256>>>(sg_b, su_b, gub, HSH);

    // 1. p = x @ Wproj + bproj
    mm_gemm<0, false><<<dim3(PP / BN, B_TOK / BM, 1), NTHR, SMEM_BYTES>>>(
        x_hi, x_lo, wp_hi, wp_lo, bproj, nullptr, p32, p_hi, p_lo,
        nullptr, nullptr, B_TOK, PP, DIN);
    // 2. router
    zero_counts_k<<<1, 32>>>(counts);
    router_k<<<B_TOK, 128>>>(p32, Wg, counts, stok, pslot, pgate);
    // 3. expert fc1 (A gathered via slot_token)
    mm_gemm<1, true><<<dim3(HH / BN, CAP / BM, EE), NTHR, SMEM_BYTES>>>(
        p_hi, p_lo, w1_hi, w1_lo, b1, nullptr, nullptr, h_hi, h_lo,
        counts, stok, CAP, HH, PP);
    // 4. expert fc2
    mm_gemm<0, false><<<dim3(PP / BN, CAP / BM, EE), NTHR, SMEM_BYTES>>>(
        h_hi, h_lo, w2_hi, w2_lo, b2, nullptr, eo32, nullptr, nullptr,
        counts, nullptr, CAP, PP, HH);
    // 5. combine
    combine_k<<<(B_TOK * PP + 255) / 256, 256>>>(eo32, pslot, pgate, moe);
    // 6. fused shared SwiGLU: one GEMM over interleaved gate/up (N = 2*HSH)
    mm_gemm<4, false><<<dim3((2 * HSH) / BN, B_TOK / BM, 1), NTHR, SMEM_BYTES>>>(
        p_hi, p_lo, guw_hi, guw_lo, gub, nullptr, nullptr, su_hi, su_lo,
        nullptr, nullptr, B_TOK, 2 * HSH, PP);
    // 7. down proj + moe residual
    mm_gemm<3, false><<<dim3(PP / BN, B_TOK / BM, 1), NTHR, SMEM_BYTES>>>(
        su_hi, su_lo, sdw_hi, sdw_lo, sd_b, moe, nullptr, cb_hi, cb_lo,
        nullptr, nullptr, B_TOK, PP, HSH);
    // 8. output MLP
    mm_gemm<1, false><<<dim3(HH / BN, B_TOK / BM, 1), NTHR, SMEM_BYTES>>>(
        cb_hi, cb_lo, m1_hi, m1_lo, m1_b, nullptr, nullptr, h1_hi, h1_lo,
        nullptr, nullptr, B_TOK, HH, PP);
    mm_gemm<0, false><<<dim3(HH / BN, B_TOK / BM, 1), NTHR, SMEM_BYTES>>>(
        h1_hi, h1_lo, m2_hi, m2_lo, m2_b, nullptr, h232, nullptr, nullptr,
        nullptr, nullptr, B_TOK, HH, HH);
    // 9. head
    head2_k<<<B_TOK / 32, 928>>>(h232, head_w, head_b, out);
}

// round 12
// speedup vs baseline: 3.0714x; 1.0299x over previous
#include <cuda_runtime.h>
#include <cuda_bf16.h>
#include <math.h>
#include <stdint.h>

// ---------------- problem constants ----------------
#define B_TOK 4096
#define DIN   512
#define PP    1024
#define HH    2048
#define EE    8
#define HSH   4096
#define OUTN  29
#define CAP   4096

// ---------------- mma.sync GEMM tile config (proven r8/r10/r11) ----------------
#define BM 128
#define BN 256
#define BKC 32
#define ROWB 80
#define OFF_AH 0
#define OFF_AL (128 * ROWB)
#define OFF_BH (256 * ROWB)
#define OFF_BL (256 * ROWB + 256 * ROWB)
#define STAGE_BYTES (768 * ROWB)
#define NSTAGE 3
#define SMEM_BYTES (NSTAGE * STAGE_BYTES)
#define NTHR 512

// ---------------- PTX helpers ----------------
__device__ __forceinline__ uint32_t smem_u32(const void* p) {
    uint32_t a;
    asm("{ .reg .u64 t; cvta.to.shared.u64 t, %1; cvt.u32.u64 %0, t; }" : "=r"(a) : "l"(p));
    return a;
}
#define CP16(dst, src) asm volatile("cp.async.cg.shared.global [%0], [%1], 16;" :: "r"(dst), "l"(src) : "memory")
#define CP_COMMIT()    asm volatile("cp.async.commit_group;" ::: "memory")

#define LDSM4(r, addr) \
    asm volatile("ldmatrix.sync.aligned.m8n8.x4.shared.b16 {%0,%1,%2,%3}, [%4];" \
        : "=r"((r)[0]), "=r"((r)[1]), "=r"((r)[2]), "=r"((r)[3]) : "r"(addr))

#define MMA_BF16(c, a, b0, b1) \
    asm volatile("mma.sync.aligned.m16n8k16.row.col.f32.bf16.bf16.f32 " \
        "{%0,%1,%2,%3}, {%4,%5,%6,%7}, {%8,%9}, {%0,%1,%2,%3};" \
        : "+f"((c)[0]), "+f"((c)[1]), "+f"((c)[2]), "+f"((c)[3]) \
        : "r"((a)[0]), "r"((a)[1]), "r"((a)[2]), "r"((a)[3]), "r"(b0), "r"(b1))

// ---------------- scratch (device globals) ----------------
#define DEV __device__ __align__(128)
DEV __nv_bfloat16 g_x_hi [B_TOK * DIN],   g_x_lo [B_TOK * DIN];
DEV __nv_bfloat16 g_p_hi [B_TOK * PP],    g_p_lo [B_TOK * PP];
DEV float         g_p32  [B_TOK * PP];
DEV __nv_bfloat16 g_h_hi [(size_t)EE * CAP * HH], g_h_lo [(size_t)EE * CAP * HH];
DEV float         g_eo32 [(size_t)EE * CAP * PP];
DEV float         g_moe  [B_TOK * PP];
DEV __nv_bfloat16 g_su_hi[(size_t)B_TOK * HSH],   g_su_lo[(size_t)B_TOK * HSH];
DEV __nv_bfloat16 g_cb_hi[B_TOK * PP],    g_cb_lo[B_TOK * PP];
DEV __nv_bfloat16 g_h1_hi[B_TOK * HH],    g_h1_lo[B_TOK * HH];
DEV float         g_h232 [B_TOK * HH];
DEV __nv_bfloat16 g_wp_hi [PP * DIN],     g_wp_lo [PP * DIN];
DEV __nv_bfloat16 g_w1_hi [EE * HH * PP], g_w1_lo [EE * HH * PP];
DEV __nv_bfloat16 g_w2_hi [EE * PP * HH], g_w2_lo [EE * PP * HH];
DEV __nv_bfloat16 g_guw_hi[(size_t)2 * HSH * PP], g_guw_lo[(size_t)2 * HSH * PP];
DEV float         g_gub   [2 * HSH];
DEV __nv_bfloat16 g_sdw_hi[PP * HSH],     g_sdw_lo[PP * HSH];
DEV __nv_bfloat16 g_m1_hi [HH * PP],      g_m1_lo [HH * PP];
DEV __nv_bfloat16 g_m2_hi [HH * HH],      g_m2_lo [HH * HH];
DEV int   g_counts[EE];
DEV int   g_slot_token[EE * CAP];
DEV int   g_pair_slot[B_TOK * 2];
DEV float g_pair_gate[B_TOK * 2];

__device__ __forceinline__ float silu_f(float x) { return x / (1.0f + expf(-x)); }

// ---------------- stage fill (512 threads): A 128 rows + B 256 rows, hi+lo ----------------
template<bool GATHER>
__device__ __forceinline__ void fill_stage(uint32_t st, int tid,
    const char* Ah, const char* Al, const char* Bh, const char* Bl,
    size_t Kb, long rowA0, long rowB0, const int* __restrict__ tokRow, size_t kByte)
{
    {
        int row = tid >> 2, ch = tid & 3;
        uint32_t d = st + row * ROWB + ch * 16;
        long arow = GATHER ? (long)tokRow[row] : (rowA0 + row);
        size_t s = (size_t)arow * Kb + kByte + ch * 16;
        CP16(d + OFF_AH, Ah + s);
        CP16(d + OFF_AL, Al + s);
    }
#pragma unroll
    for (int i = 0; i < 2; i++) {
        int p = tid + (i << 9);
        int row = p >> 2, ch = p & 3;
        uint32_t d = st + row * ROWB + ch * 16;
        size_t s = (size_t)(rowB0 + row) * Kb + kByte + ch * 16;
        CP16(d + OFF_BH, Bh + s);
        CP16(d + OFF_BL, Bl + s);
    }
    CP_COMMIT();
}

// ---------------- bf16-split x3 GEMM, 16 warps, warp tile 32x64 ----------------
// MODE: 0=+bias 1=silu(+bias) 3=(+bias)+extra 4=fused SwiGLU pairs (even=gate, odd=up)
template<int MODE, bool GATHER>
__global__ __launch_bounds__(NTHR, 1)
void mm_gemm(const __nv_bfloat16* __restrict__ Ahi, const __nv_bfloat16* __restrict__ Alo,
             const __nv_bfloat16* __restrict__ Bhi, const __nv_bfloat16* __restrict__ Blo,
             const float* __restrict__ bias, const float* __restrict__ extra,
             float* __restrict__ C32, __nv_bfloat16* __restrict__ Chi,
             __nv_bfloat16* __restrict__ Clo,
             const int* __restrict__ counts, const int* __restrict__ stok,
             int capRows, int N, int K)
{
    const int z  = blockIdx.z;
    const int m0 = blockIdx.y * BM;
    const int n0 = blockIdx.x * BN;
    int cnt = capRows;
    if (counts) { cnt = counts[z]; if (m0 >= cnt) return; }

    extern __shared__ __align__(128) char smem[];
    const uint32_t sb = smem_u32(smem);
    const int tid = threadIdx.x, lane = tid & 31, wid = tid >> 5;
    const int warp_m = wid & 3;
    const int warp_n = wid >> 2;

    const size_t Kb = (size_t)K * 2;
    const long rowA0 = (long)z * capRows + m0;
    const long rowB0 = (long)z * N + n0;
    const int* tokRow = GATHER ? (stok + z * CAP + m0) : nullptr;
    const int  C = K / BKC;

    float acc[2][8][4];
#pragma unroll
    for (int i = 0; i < 2; i++)
#pragma unroll
        for (int j = 0; j < 8; j++)
#pragma unroll
            for (int q = 0; q < 4; q++) acc[i][j][q] = 0.f;

    const char* Ah = (const char*)Ahi; const char* Al = (const char*)Alo;
    const char* Bh = (const char*)Bhi; const char* Bl = (const char*)Blo;

    fill_stage<GATHER>(sb, tid, Ah, Al, Bh, Bl, Kb, rowA0, rowB0, tokRow, 0);
    if (C > 1) fill_stage<GATHER>(sb + STAGE_BYTES, tid, Ah, Al, Bh, Bl, Kb, rowA0, rowB0, tokRow, 64);

    const int lm = lane & 15;
    const int lkb = (lane >> 4) << 4;

    for (int c = 0; c < C; c++) {
        if (c + 2 < C) asm volatile("cp.async.wait_group 1;" ::: "memory");
        else           asm volatile("cp.async.wait_group 0;" ::: "memory");
        __syncthreads();
        if (c + 2 < C)
            fill_stage<GATHER>(sb + ((c + 2) % NSTAGE) * STAGE_BYTES, tid, Ah, Al, Bh, Bl,
                               Kb, rowA0, rowB0, tokRow, (size_t)(c + 2) * 64);

        const uint32_t stg = sb + (c % NSTAGE) * STAGE_BYTES;
#pragma unroll
        for (int kk = 0; kk < 2; kk++) {
            const uint32_t kb = kk * 32 + lkb;
            uint32_t a_h[2][4], a_l[2][4];
#pragma unroll
            for (int mt = 0; mt < 2; mt++) {
                uint32_t ad = stg + (warp_m * 32 + mt * 16 + lm) * ROWB + kb;
                LDSM4(a_h[mt], ad + OFF_AH);
                LDSM4(a_l[mt], ad + OFF_AL);
            }
#pragma unroll
            for (int n2 = 0; n2 < 4; n2++) {
                uint32_t b_h[4], b_l[4];
                uint32_t bd = stg + (warp_n * 64 + n2 * 16 + lm) * ROWB + kb;
                LDSM4(b_h, bd + OFF_BH);
                LDSM4(b_l, bd + OFF_BL);
#pragma unroll
                for (int mt = 0; mt < 2; mt++)
#pragma unroll
                    for (int o = 0; o < 2; o++) {
                        const int nt = n2 * 2 + o;
                        MMA_BF16(acc[mt][nt], a_h[mt], b_h[o], b_h[o + 2]);
                        MMA_BF16(acc[mt][nt], a_h[mt], b_l[o], b_l[o + 2]);
                        MMA_BF16(acc[mt][nt], a_l[mt], b_h[o], b_h[o + 2]);
                    }
            }
        }
    }

    // ---- epilogue ----
    const float* biasz = bias + (size_t)z * N;
#pragma unroll
    for (int mt = 0; mt < 2; mt++) {
#pragma unroll
        for (int half = 0; half < 2; half++) {
            const int rtile = warp_m * 32 + mt * 16 + (lane >> 2) + half * 8;
            if (m0 + rtile >= cnt) continue;
            const size_t gr = (size_t)z * capRows + m0 + rtile;
#pragma unroll
            for (int nt = 0; nt < 8; nt++) {
                const int col = n0 + warp_n * 64 + nt * 8 + (lane & 3) * 2;
                float v0 = acc[mt][nt][half * 2 + 0] + biasz[col];
                float v1 = acc[mt][nt][half * 2 + 1] + biasz[col + 1];
                if (MODE == 4) {
                    float w = silu_f(v0) * v1;
                    __nv_bfloat16 h = __float2bfloat16(w);
                    const size_t o = gr * (size_t)(N >> 1) + (col >> 1);
                    Chi[o] = h;
                    Clo[o] = __float2bfloat16(w - __bfloat162float(h));
                    continue;
                }
                if (MODE == 1) { v0 = silu_f(v0); v1 = silu_f(v1); }
                if (MODE == 3) {
                    const float2 e = *(const float2*)&extra[gr * N + col];
                    v0 += e.x; v1 += e.y;
                }
                if (C32) { float2 w = {v0, v1}; *(float2*)&C32[gr * N + col] = w; }
                if (Chi) {
                    __nv_bfloat16 h0 = __float2bfloat16(v0);
                    __nv_bfloat16 h1 = __float2bfloat16(v1);
                    __nv_bfloat162 hp; hp.x = h0; hp.y = h1;
                    *(__nv_bfloat162*)&Chi[gr * N + col] = hp;
                    __nv_bfloat162 lp;
                    lp.x = __float2bfloat16(v0 - __bfloat162float(h0));
                    lp.y = __float2bfloat16(v1 - __bfloat162float(h1));
                    *(__nv_bfloat162*)&Clo[gr * N + col] = lp;
                }
            }
        }
    }
}

// ---------------- small kernels ----------------
__global__ void conv_split_k(const float* __restrict__ in, __nv_bfloat16* __restrict__ hi,
                             __nv_bfloat16* __restrict__ lo, size_t n)
{
    size_t i = (size_t)blockIdx.x * blockDim.x + threadIdx.x;
    if (i >= n) return;
    float v = in[i];
    __nv_bfloat16 h = __float2bfloat16(v);
    hi[i] = h;
    lo[i] = __float2bfloat16(v - __bfloat162float(h));
}

// vectorized transpose + split: W [z, K, N] -> out [(z*N + n)*RMUL + radd, k]
template<int RMUL>
__global__ __launch_bounds__(256)
void convT2_k(const float* __restrict__ W, __nv_bfloat16* __restrict__ hi,
              __nv_bfloat16* __restrict__ lo, int K, int N, int radd)
{
    __shared__ float t[32][129];
    const int k0 = blockIdx.y * 32, n0 = blockIdx.x * 128;
    const float* Wz = W + (size_t)blockIdx.z * K * N;
    const int tid = threadIdx.x;
    {
        const int c = tid & 127;
        for (int r = tid >> 7; r < 32; r += 2)
            t[r][c] = Wz[(size_t)(k0 + r) * N + n0 + c];
    }
    __syncthreads();
    const size_t zbase = (size_t)blockIdx.z * N * RMUL;
    for (int idx = tid; idx < 128 * 16; idx += 256) {
        const int n = idx >> 4, kp = idx & 15;
        float v0 = t[kp * 2][n], v1 = t[kp * 2 + 1][n];
        __nv_bfloat16 h0 = __float2bfloat16(v0), h1 = __float2bfloat16(v1);
        __nv_bfloat162 hp; hp.x = h0; hp.y = h1;
        __nv_bfloat162 lp;
        lp.x = __float2bfloat16(v0 - __bfloat162float(h0));
        lp.y = __float2bfloat16(v1 - __bfloat162float(h1));
        const size_t orow = zbase + (size_t)(n0 + n) * RMUL + radd;
        const size_t o = orow * K + k0 + kp * 2;
        *(__nv_bfloat162*)&hi[o] = hp;
        *(__nv_bfloat162*)&lo[o] = lp;
    }
}

__global__ void ileave_bias_k(const float* __restrict__ a, const float* __restrict__ b,
                              float* __restrict__ o, int n)
{
    int i = blockIdx.x * 256 + threadIdx.x;
    if (i < n) { o[2 * i] = a[i]; o[2 * i + 1] = b[i]; }
}

__global__ void zero_counts_k(int* counts) { if (threadIdx.x < EE) counts[threadIdx.x] = 0; }

__global__ void router_k(const float* __restrict__ p, const float* __restrict__ Wg,
                         int* __restrict__ counts, int* __restrict__ slot_token,
                         int* __restrict__ pair_slot, float* __restrict__ pair_gate)
{
    const int t = blockIdx.x;
    const int tid = threadIdx.x; // 128
    __shared__ float red[EE][128];
    float acc[EE];
#pragma unroll
    for (int e = 0; e < EE; e++) acc[e] = 0.f;
    const float* pr = p + (size_t)t * PP;
    for (int j = tid; j < PP; j += 128) {
        float pv = pr[j];
        const float* wg = Wg + (size_t)j * EE;
#pragma unroll
        for (int e = 0; e < EE; e++) acc[e] += pv * wg[e];
    }
#pragma unroll
    for (int e = 0; e < EE; e++) red[e][tid] = acc[e];
    __syncthreads();
    if (tid == 0) {
        float logit[EE];
        for (int e = 0; e < EE; e++) {
            float s = 0.f;
            for (int i = 0; i < 128; i++) s += red[e][i];
            logit[e] = s;
        }
        int i0 = 0;
        for (int e = 1; e < EE; e++) if (logit[e] > logit[i0]) i0 = e;
        int i1 = (i0 == 0) ? 1 : 0;
        for (int e = 0; e < EE; e++) {
            if (e == i0) continue;
            if (logit[e] > logit[i1]) i1 = e;
        }
        float g0 = 1.f / (1.f + expf(logit[i1] - logit[i0]));
        float g1 = 1.f - g0;
        int s0 = atomicAdd(&counts[i0], 1);
        int s1 = atomicAdd(&counts[i1], 1);
        slot_token[i0 * CAP + s0] = t;
        slot_token[i1 * CAP + s1] = t;
        pair_slot[2 * t]     = i0 * CAP + s0;
        pair_slot[2 * t + 1] = i1 * CAP + s1;
        pair_gate[2 * t]     = g0;
        pair_gate[2 * t + 1] = g1;
    }
}

__global__ void combine_k(const float* __restrict__ eo, const int* __restrict__ pair_slot,
                          const float* __restrict__ pair_gate, float* __restrict__ moe)
{
    int idx = blockIdx.x * blockDim.x + threadIdx.x;
    if (idx >= B_TOK * PP) return;
    int t = idx >> 10, j = idx & (PP - 1);
    int s0 = pair_slot[2 * t], s1 = pair_slot[2 * t + 1];
    float g0 = pair_gate[2 * t], g1 = pair_gate[2 * t + 1];
    moe[idx] = g0 * eo[(size_t)s0 * PP + j] + g1 * eo[(size_t)s1 * PP + j];
}

// ---------------- head: tiled, 32 tokens per block ----------------
#define HKC 128
__global__ __launch_bounds__(928)
void head2_k(const float* __restrict__ hid2, const float* __restrict__ head_w,
             const float* __restrict__ head_b, float* __restrict__ out)
{
    __shared__ float hs[32 * HKC];
    __shared__ float ws[HKC * 30];
    const int tid = threadIdx.x;
    const int tok0 = blockIdx.x * 32;
    const int tokl = tid / OUTN;
    const int o    = tid % OUTN;
    float acc = 0.f;

    for (int kc = 0; kc < HH; kc += HKC) {
        for (int i = tid; i < 32 * HKC; i += 928)
            hs[i] = hid2[(size_t)(tok0 + (i >> 7)) * HH + kc + (i & (HKC - 1))];
        for (int i = tid; i < HKC * OUTN; i += 928) {
            int k = i / OUTN, oo = i % OUTN;
            ws[k * 30 + oo] = head_w[(size_t)(kc + k) * OUTN + oo];
        }
        __syncthreads();
        const float* hrow = hs + tokl * HKC;
#pragma unroll 4
        for (int k = 0; k < HKC; k++)
            acc += hrow[k] * ws[k * 30 + o];
        __syncthreads();
    }
    out[(size_t)(tok0 + tokl) * OUTN + o] = acc + head_b[o];
}

// ---------------- launch ----------------
template <typename T>
static T* symaddr(const void* sym) { void* p = nullptr; cudaGetSymbolAddress(&p, sym); return (T*)p; }

extern "C" void kernel_launch(void* const* d_in, const int* in_sizes, int n_in,
                              void* d_out, int out_size)
{
    const float* x      = (const float*)d_in[0];
    const float* Wproj  = (const float*)d_in[1];
    const float* bproj  = (const float*)d_in[2];
    const float* Wg     = (const float*)d_in[3];
    const float* W1     = (const float*)d_in[4];
    const float* b1     = (const float*)d_in[5];
    const float* W2     = (const float*)d_in[6];
    const float* b2     = (const float*)d_in[7];
    const float* sg_w   = (const float*)d_in[8];
    const float* sg_b   = (const float*)d_in[9];
    const float* su_w   = (const float*)d_in[10];
    const float* su_b   = (const float*)d_in[11];
    const float* sd_w   = (const float*)d_in[12];
    const float* sd_b   = (const float*)d_in[13];
    const float* m1_w   = (const float*)d_in[14];
    const float* m1_b   = (const float*)d_in[15];
    const float* m2_w   = (const float*)d_in[16];
    const float* m2_b   = (const float*)d_in[17];
    const float* head_w = (const float*)d_in[18];
    const float* head_b = (const float*)d_in[19];
    float* out = (float*)d_out;

    static cudaStream_t s1 = nullptr;
    static cudaEvent_t evFork, evP, evW1, evW2, evSw;
    if (!s1) {
        cudaStreamCreateWithFlags(&s1, cudaStreamNonBlocking);
        cudaEventCreateWithFlags(&evFork, cudaEventDisableTiming);
        cudaEventCreateWithFlags(&evP,    cudaEventDisableTiming);
        cudaEventCreateWithFlags(&evW1,   cudaEventDisableTiming);
        cudaEventCreateWithFlags(&evW2,   cudaEventDisableTiming);
        cudaEventCreateWithFlags(&evSw,   cudaEventDisableTiming);
        cudaFuncSetAttribute(mm_gemm<0, false>, cudaFuncAttributeMaxDynamicSharedMemorySize, SMEM_BYTES);
        cudaFuncSetAttribute(mm_gemm<1, false>, cudaFuncAttributeMaxDynamicSharedMemorySize, SMEM_BYTES);
        cudaFuncSetAttribute(mm_gemm<3, false>, cudaFuncAttributeMaxDynamicSharedMemorySize, SMEM_BYTES);
        cudaFuncSetAttribute(mm_gemm<4, false>, cudaFuncAttributeMaxDynamicSharedMemorySize, SMEM_BYTES);
        cudaFuncSetAttribute(mm_gemm<1, true>,  cudaFuncAttributeMaxDynamicSharedMemorySize, SMEM_BYTES);
    }

    __nv_bfloat16 *x_hi = symaddr<__nv_bfloat16>(g_x_hi),  *x_lo = symaddr<__nv_bfloat16>(g_x_lo);
    __nv_bfloat16 *p_hi = symaddr<__nv_bfloat16>(g_p_hi),  *p_lo = symaddr<__nv_bfloat16>(g_p_lo);
    float *p32  = symaddr<float>(g_p32);
    __nv_bfloat16 *h_hi  = symaddr<__nv_bfloat16>(g_h_hi),  *h_lo  = symaddr<__nv_bfloat16>(g_h_lo);
    float *eo32 = symaddr<float>(g_eo32);
    float *moe  = symaddr<float>(g_moe);
    __nv_bfloat16 *su_hi = symaddr<__nv_bfloat16>(g_su_hi), *su_lo = symaddr<__nv_bfloat16>(g_su_lo);
    __nv_bfloat16 *cb_hi = symaddr<__nv_bfloat16>(g_cb_hi), *cb_lo = symaddr<__nv_bfloat16>(g_cb_lo);
    __nv_bfloat16 *h1_hi = symaddr<__nv_bfloat16>(g_h1_hi), *h1_lo = symaddr<__nv_bfloat16>(g_h1_lo);
    float *h232 = symaddr<float>(g_h232);
    __nv_bfloat16 *wp_hi = symaddr<__nv_bfloat16>(g_wp_hi), *wp_lo = symaddr<__nv_bfloat16>(g_wp_lo);
    __nv_bfloat16 *w1_hi = symaddr<__nv_bfloat16>(g_w1_hi), *w1_lo = symaddr<__nv_bfloat16>(g_w1_lo);
    __nv_bfloat16 *w2_hi = symaddr<__nv_bfloat16>(g_w2_hi), *w2_lo = symaddr<__nv_bfloat16>(g_w2_lo);
    __nv_bfloat16 *guw_hi = symaddr<__nv_bfloat16>(g_guw_hi), *guw_lo = symaddr<__nv_bfloat16>(g_guw_lo);
    float *gub = symaddr<float>(g_gub);
    __nv_bfloat16 *sdw_hi = symaddr<__nv_bfloat16>(g_sdw_hi), *sdw_lo = symaddr<__nv_bfloat16>(g_sdw_lo);
    __nv_bfloat16 *m1_hi = symaddr<__nv_bfloat16>(g_m1_hi), *m1_lo = symaddr<__nv_bfloat16>(g_m1_lo);
    __nv_bfloat16 *m2_hi = symaddr<__nv_bfloat16>(g_m2_hi), *m2_lo = symaddr<__nv_bfloat16>(g_m2_lo);
    int *counts = symaddr<int>(g_counts);
    int *stok   = symaddr<int>(g_slot_token);
    int *pslot  = symaddr<int>(g_pair_slot);
    float *pgate = symaddr<float>(g_pair_gate);

    // ---- fork side stream ----
    cudaEventRecord(evFork, 0);
    cudaStreamWaitEvent(s1, evFork, 0);

    // side stream s1: all heavy weight transposes (overlap GEMM-1 + router)
    convT2_k<1><<<dim3(HH / 128, PP / 32, EE),  256, 0, s1>>>(W1, w1_hi, w1_lo, PP, HH, 0);
    cudaEventRecord(evW1, s1);
    convT2_k<1><<<dim3(PP / 128, HH / 32, EE),  256, 0, s1>>>(W2, w2_hi, w2_lo, HH, PP, 0);
    cudaEventRecord(evW2, s1);
    convT2_k<2><<<dim3(HSH / 128, PP / 32, 1),  256, 0, s1>>>(sg_w, guw_hi, guw_lo, PP, HSH, 0);
    convT2_k<2><<<dim3(HSH / 128, PP / 32, 1),  256, 0, s1>>>(su_w, guw_hi, guw_lo, PP, HSH, 1);
    ileave_bias_k<<<(HSH + 255) / 256, 256, 0, s1>>>(sg_b, su_b, gub, HSH);
    convT2_k<1><<<dim3(PP / 128, HSH / 32, 1),  256, 0, s1>>>(sd_w, sdw_hi, sdw_lo, HSH, PP, 0);
    convT2_k<1><<<dim3(HH / 128, PP / 32, 1),   256, 0, s1>>>(m1_w, m1_hi, m1_lo, PP, HH, 0);
    convT2_k<1><<<dim3(HH / 128, HH / 32, 1),   256, 0, s1>>>(m2_w, m2_hi, m2_lo, HH, HH, 0);

    // main stream: input split + proj GEMM + router
    conv_split_k<<<(B_TOK * DIN + 255) / 256, 256>>>(x, x_hi, x_lo, (size_t)B_TOK * DIN);
    convT2_k<1><<<dim3(PP / 128, DIN / 32, 1),  256>>>(Wproj, wp_hi, wp_lo, DIN, PP, 0);
    mm_gemm<0, false><<<dim3(PP / BN, B_TOK / BM, 1), NTHR, SMEM_BYTES>>>(
        x_hi, x_lo, wp_hi, wp_lo, bproj, nullptr, p32, p_hi, p_lo,
        nullptr, nullptr, B_TOK, PP, DIN);
    cudaEventRecord(evP, 0);                      // p_hi/p_lo ready
    zero_counts_k<<<1, 32>>>(counts);
    router_k<<<B_TOK, 128>>>(p32, Wg, counts, stok, pslot, pgate);

    // s1: fused shared SwiGLU (needs p + guw) -- overlaps expert chain on main stream
    cudaStreamWaitEvent(s1, evP, 0);
    mm_gemm<4, false><<<dim3((2 * HSH) / BN, B_TOK / BM, 1), NTHR, SMEM_BYTES, s1>>>(
        p_hi, p_lo, guw_hi, guw_lo, gub, nullptr, nullptr, su_hi, su_lo,
        nullptr, nullptr, B_TOK, 2 * HSH, PP);
    cudaEventRecord(evSw, s1);

    // main stream: expert fc1 (wait W1), fc2 (wait W2), combine
    cudaStreamWaitEvent(0, evW1, 0);
    mm_gemm<1, true><<<dim3(HH / BN, CAP / BM, EE), NTHR, SMEM_BYTES>>>(
        p_hi, p_lo, w1_hi, w1_lo, b1, nullptr, nullptr, h_hi, h_lo,
        counts, stok, CAP, HH, PP);
    cudaStreamWaitEvent(0, evW2, 0);
    mm_gemm<0, false><<<dim3(PP / BN, CAP / BM, EE), NTHR, SMEM_BYTES>>>(
        h_hi, h_lo, w2_hi, w2_lo, b2, nullptr, eo32, nullptr, nullptr,
        counts, nullptr, CAP, PP, HH);
    combine_k<<<(B_TOK * PP + 255) / 256, 256>>>(eo32, pslot, pgate, moe);

    // join: down proj needs su (s1) + moe + sdw (s1, ordered before evSw)
    cudaStreamWaitEvent(0, evSw, 0);
    mm_gemm<3, false><<<dim3(PP / BN, B_TOK / BM, 1), NTHR, SMEM_BYTES>>>(
        su_hi, su_lo, sdw_hi, sdw_lo, sd_b, moe, nullptr, cb_hi, cb_lo,
        nullptr, nullptr, B_TOK, PP, HSH);
    // output MLP
    mm_gemm<1, false><<<dim3(HH / BN, B_TOK / BM, 1), NTHR, SMEM_BYTES>>>(
        cb_hi, cb_lo, m1_hi, m1_lo, m1_b, nullptr, nullptr, h1_hi, h1_lo,
        nullptr, nullptr, B_TOK, HH, PP);
    mm_gemm<0, false><<<dim3(HH / BN, B_TOK / BM, 1), NTHR, SMEM_BYTES>>>(
        h1_hi, h1_lo, m2_hi, m2_lo, m2_b, nullptr, h232, nullptr, nullptr,
        nullptr, nullptr, B_TOK, HH, HH);
    // head
    head2_k<<<B_TOK / 32, 928>>>(h232, head_w, head_b, out);
}